// round 1
// baseline (speedup 1.0000x reference)
#include <cuda_runtime.h>
#include <cuda_bf16.h>
#include <math.h>

// Problem constants
#define BATCH 2
#define SEQ 2048
#define DIM 768
#define NHEAD 12
#define HDIM 64
#define QKV_DIM (3 * DIM)     // 2304
#define M_TOTAL (BATCH * SEQ) // 4096
#define SCALE 0.125f          // 64^-0.5
#define MASK_VAL -10000000.0f

// Scratch (device globals; no allocations allowed)
__device__ float g_q[BATCH * NHEAD * SEQ * HDIM];
__device__ float g_k[BATCH * NHEAD * SEQ * HDIM];
__device__ float g_v[BATCH * NHEAD * SEQ * HDIM];
__device__ float g_x[BATCH * SEQ * DIM];

// ---------------------------------------------------------------------------
// Kernel 1: QKV projection. C[m, d] = sum_c A[m, c] * W[d, c]
// A: [4096, 768], W: [2304, 768]. Output scattered into g_q/g_k/g_v with
// layout [b, h, n, hd] so attention loads are coalesced.
// Tile: 64x64 per block, 256 threads, 4x4 micro-tile, K-chunk 16.
// ---------------------------------------------------------------------------
__global__ __launch_bounds__(256) void qkv_kernel(
    const float* __restrict__ A, const float* __restrict__ W)
{
    __shared__ float As[16 * 65]; // As[c][r], padded
    __shared__ float Ws[16 * 65]; // Ws[c][r], padded

    const int tid = threadIdx.x;
    const int tx = tid & 15;
    const int ty = tid >> 4;
    const int m0 = blockIdx.y * 64;
    const int d0 = blockIdx.x * 64;

    float acc[4][4];
#pragma unroll
    for (int i = 0; i < 4; i++)
#pragma unroll
        for (int j = 0; j < 4; j++) acc[i][j] = 0.f;

    for (int k0 = 0; k0 < DIM; k0 += 16) {
#pragma unroll
        for (int l = tid; l < 64 * 16; l += 256) {
            int r = l >> 4, c = l & 15;
            As[c * 65 + r] = A[(size_t)(m0 + r) * DIM + k0 + c];
            Ws[c * 65 + r] = W[(size_t)(d0 + r) * DIM + k0 + c];
        }
        __syncthreads();
#pragma unroll
        for (int c = 0; c < 16; c++) {
            float a[4], w[4];
#pragma unroll
            for (int i = 0; i < 4; i++) a[i] = As[c * 65 + ty * 4 + i];
#pragma unroll
            for (int j = 0; j < 4; j++) w[j] = Ws[c * 65 + tx * 4 + j];
#pragma unroll
            for (int i = 0; i < 4; i++)
#pragma unroll
                for (int j = 0; j < 4; j++)
                    acc[i][j] = fmaf(a[i], w[j], acc[i][j]);
        }
        __syncthreads();
    }

    // Scatter epilogue: tile (d0..d0+63) lies in exactly one (which, head).
    const int which = d0 / DIM;            // 0=q, 1=k, 2=v
    const int h = (d0 % DIM) / HDIM;       // head
    float* dst = (which == 0) ? g_q : (which == 1) ? g_k : g_v;

#pragma unroll
    for (int i = 0; i < 4; i++) {
        int m = m0 + ty * 4 + i;
        int b = m >> 11;        // / 2048
        int n = m & 2047;
        size_t base = ((size_t)(b * NHEAD + h) * SEQ + n) * HDIM;
#pragma unroll
        for (int j = 0; j < 4; j++) {
            dst[base + tx * 4 + j] = acc[i][j];
        }
    }
}

// ---------------------------------------------------------------------------
// Kernel 2: flash-style attention per (b, h). 64 queries/block, 64 threads.
// One thread owns one query row: s[64] scores + o[64] accumulator in regs.
// K and V share the KVs smem buffer (two phases per kv-tile).
// Output written to g_x in [b, n, h*64 + d] layout.
// ---------------------------------------------------------------------------
__global__ __launch_bounds__(64) void attn_kernel(const int* __restrict__ mask)
{
    __shared__ float Qs[64 * 65];
    __shared__ float KVs[64 * 64];
    __shared__ int Ms[64];

    const int row = threadIdx.x;      // query row within tile (0..63)
    const int bh = blockIdx.y;        // 0..23
    const int q0 = blockIdx.x * 64;
    const int b = bh / NHEAD;
    const int h = bh % NHEAD;

    const float* qbase = g_q + (size_t)bh * SEQ * HDIM;
    const float* kbase = g_k + (size_t)bh * SEQ * HDIM;
    const float* vbase = g_v + (size_t)bh * SEQ * HDIM;

    // Load Q tile (padded rows)
    for (int l = row; l < 64 * 64; l += 64) {
        int r = l >> 6, d = l & 63;
        Qs[r * 65 + d] = qbase[(size_t)(q0 + r) * HDIM + d];
    }

    float o[HDIM];
#pragma unroll
    for (int d = 0; d < HDIM; d++) o[d] = 0.f;
    float mrun = -INFINITY;
    float lrun = 0.f;

    __syncthreads();

    for (int k0 = 0; k0 < SEQ; k0 += 64) {
        // ---- phase 1: K tile + mask ----
        for (int l = row; l < 64 * 64; l += 64)
            KVs[l] = kbase[(size_t)k0 * HDIM + l];
        Ms[row] = mask[b * SEQ + k0 + row];
        __syncthreads();

        float s[64];
#pragma unroll
        for (int j = 0; j < 64; j++) s[j] = 0.f;

        for (int d = 0; d < HDIM; d++) {
            float qd = Qs[row * 65 + d];
#pragma unroll
            for (int j = 0; j < 64; j++)
                s[j] = fmaf(qd, KVs[j * 64 + d], s[j]);
        }

        float mt = -INFINITY;
#pragma unroll
        for (int j = 0; j < 64; j++) {
            s[j] = (Ms[j] > 0) ? MASK_VAL : s[j] * SCALE;
            mt = fmaxf(mt, s[j]);
        }
        float mnew = fmaxf(mrun, mt);
        float alpha = __expf(mrun - mnew); // exp(-inf)=0 on first tile
        float lsum = 0.f;
#pragma unroll
        for (int j = 0; j < 64; j++) {
            s[j] = __expf(s[j] - mnew);
            lsum += s[j];
        }
        lrun = lrun * alpha + lsum;
        mrun = mnew;
#pragma unroll
        for (int d = 0; d < HDIM; d++) o[d] *= alpha;

        __syncthreads();
        // ---- phase 2: V tile (reuse KVs) ----
        for (int l = row; l < 64 * 64; l += 64)
            KVs[l] = vbase[(size_t)k0 * HDIM + l];
        __syncthreads();

#pragma unroll
        for (int j = 0; j < 64; j++) {
            float p = s[j];
#pragma unroll
            for (int d = 0; d < HDIM; d++)
                o[d] = fmaf(p, KVs[j * 64 + d], o[d]);
        }
        __syncthreads();
    }

    const float inv = 1.f / lrun;
    float* dst = g_x + ((size_t)(b * SEQ + q0 + row)) * DIM + h * HDIM;
#pragma unroll
    for (int d = 0; d < HDIM; d++) dst[d] = o[d] * inv;
}

// ---------------------------------------------------------------------------
// Kernel 3: FC projection. out[m, d] = sum_c x[m, c] * Wfc[d, c] + b[d]
// x = g_x [4096, 768], Wfc [768, 768].
// ---------------------------------------------------------------------------
__global__ __launch_bounds__(256) void fc_kernel(
    const float* __restrict__ W, const float* __restrict__ bias,
    float* __restrict__ out)
{
    __shared__ float As[16 * 65];
    __shared__ float Ws[16 * 65];

    const int tid = threadIdx.x;
    const int tx = tid & 15;
    const int ty = tid >> 4;
    const int m0 = blockIdx.y * 64;
    const int d0 = blockIdx.x * 64;

    float acc[4][4];
#pragma unroll
    for (int i = 0; i < 4; i++)
#pragma unroll
        for (int j = 0; j < 4; j++) acc[i][j] = 0.f;

    for (int k0 = 0; k0 < DIM; k0 += 16) {
#pragma unroll
        for (int l = tid; l < 64 * 16; l += 256) {
            int r = l >> 4, c = l & 15;
            As[c * 65 + r] = g_x[(size_t)(m0 + r) * DIM + k0 + c];
            Ws[c * 65 + r] = W[(size_t)(d0 + r) * DIM + k0 + c];
        }
        __syncthreads();
#pragma unroll
        for (int c = 0; c < 16; c++) {
            float a[4], w[4];
#pragma unroll
            for (int i = 0; i < 4; i++) a[i] = As[c * 65 + ty * 4 + i];
#pragma unroll
            for (int j = 0; j < 4; j++) w[j] = Ws[c * 65 + tx * 4 + j];
#pragma unroll
            for (int i = 0; i < 4; i++)
#pragma unroll
                for (int j = 0; j < 4; j++)
                    acc[i][j] = fmaf(a[i], w[j], acc[i][j]);
        }
        __syncthreads();
    }

#pragma unroll
    for (int i = 0; i < 4; i++) {
        int m = m0 + ty * 4 + i;
#pragma unroll
        for (int j = 0; j < 4; j++) {
            int d = d0 + tx * 4 + j;
            out[(size_t)m * DIM + d] = acc[i][j] + bias[d];
        }
    }
}

// ---------------------------------------------------------------------------
// Launch
// ---------------------------------------------------------------------------
extern "C" void kernel_launch(void* const* d_in, const int* in_sizes, int n_in,
                              void* d_out, int out_size)
{
    const float* inputs = (const float*)d_in[0];
    const int*   pmask  = (const int*)d_in[1];
    const float* w_qkv  = (const float*)d_in[2];
    const float* w_fc   = (const float*)d_in[3];
    const float* b_fc   = (const float*)d_in[4];
    float* out = (float*)d_out;

    {
        dim3 grid(QKV_DIM / 64, M_TOTAL / 64); // (36, 64)
        qkv_kernel<<<grid, 256>>>(inputs, w_qkv);
    }
    {
        dim3 grid(SEQ / 64, BATCH * NHEAD);    // (32, 24)
        attn_kernel<<<grid, 64>>>(pmask);
    }
    {
        dim3 grid(DIM / 64, M_TOTAL / 64);     // (12, 64)
        fc_kernel<<<grid, 256>>>(w_fc, b_fc, out);
    }
}

// round 2
// speedup vs baseline: 1.8264x; 1.8264x over previous
#include <cuda_runtime.h>
#include <cuda_bf16.h>
#include <math.h>

// Problem constants
#define BATCH 2
#define SEQ 2048
#define DIM 768
#define NHEAD 12
#define HDIM 64
#define QKV_DIM (3 * DIM)     // 2304
#define M_TOTAL (BATCH * SEQ) // 4096
#define SCALE 0.125f          // 64^-0.5

// Scratch (device globals; no allocations allowed)
__device__ float g_q[BATCH * NHEAD * SEQ * HDIM];
__device__ float g_k[BATCH * NHEAD * SEQ * HDIM];
__device__ float g_v[BATCH * NHEAD * SEQ * HDIM];
__device__ float g_x[M_TOTAL * DIM];
__device__ int   g_idx[BATCH * SEQ];
__device__ int   g_cnt[BATCH];

// ---------------------------------------------------------------------------
// Kernel 0: per-batch compaction of unmasked key indices (mask <= 0).
// Masked keys (mask > 0) get score MASK_VAL=-1e7; exp underflows to exactly 0
// in fp32, so dropping them is numerically identical to the reference.
// ---------------------------------------------------------------------------
__global__ void compact_kernel(const int* __restrict__ mask)
{
    __shared__ int cnts[256];
    const int b = blockIdx.x;
    const int t = threadIdx.x;
    const int PER = SEQ / 256; // 8

    int m[PER];
    int local = 0;
#pragma unroll
    for (int i = 0; i < PER; i++) {
        m[i] = mask[b * SEQ + t * PER + i];
        local += (m[i] <= 0);
    }
    cnts[t] = local;
    __syncthreads();
    // Hillis-Steele inclusive scan
    for (int off = 1; off < 256; off <<= 1) {
        int v = (t >= off) ? cnts[t - off] : 0;
        __syncthreads();
        cnts[t] += v;
        __syncthreads();
    }
    int w = cnts[t] - local;
#pragma unroll
    for (int i = 0; i < PER; i++)
        if (m[i] <= 0) g_idx[b * SEQ + (w++)] = t * PER + i;
    if (t == 255) g_cnt[b] = cnts[255];
}

// ---------------------------------------------------------------------------
// Kernel 1: QKV projection. C[m, d] = sum_c A[m, c] * W[d, c]  (NT GEMM)
// 128x128 tile, 256 threads, 8x8 micro-tile (split 4+4), K-chunk 16,
// register-prefetch pipelining, float4 smem reads.
// ---------------------------------------------------------------------------
__global__ __launch_bounds__(256) void qkv_kernel(
    const float* __restrict__ A, const float* __restrict__ W)
{
    __shared__ float As[16][132];
    __shared__ float Ws[16][132];

    const int tid = threadIdx.x;
    const int tx = tid & 15;
    const int ty = tid >> 4;
    const int m0 = blockIdx.y << 7;
    const int d0 = blockIdx.x << 7;

    float acc[8][8];
#pragma unroll
    for (int i = 0; i < 8; i++)
#pragma unroll
        for (int j = 0; j < 8; j++) acc[i][j] = 0.f;

    const int r0 = tid >> 2,        c0 = (tid & 3) << 2;
    const int r1 = (tid + 256) >> 2, c1 = (tid & 3) << 2;

    float4 ra0 = *(const float4*)&A[(size_t)(m0 + r0) * DIM + c0];
    float4 ra1 = *(const float4*)&A[(size_t)(m0 + r1) * DIM + c1];
    float4 rw0 = *(const float4*)&W[(size_t)(d0 + r0) * DIM + c0];
    float4 rw1 = *(const float4*)&W[(size_t)(d0 + r1) * DIM + c1];

    for (int k0 = 0; k0 < DIM; k0 += 16) {
        As[c0 + 0][r0] = ra0.x; As[c0 + 1][r0] = ra0.y; As[c0 + 2][r0] = ra0.z; As[c0 + 3][r0] = ra0.w;
        As[c1 + 0][r1] = ra1.x; As[c1 + 1][r1] = ra1.y; As[c1 + 2][r1] = ra1.z; As[c1 + 3][r1] = ra1.w;
        Ws[c0 + 0][r0] = rw0.x; Ws[c0 + 1][r0] = rw0.y; Ws[c0 + 2][r0] = rw0.z; Ws[c0 + 3][r0] = rw0.w;
        Ws[c1 + 0][r1] = rw1.x; Ws[c1 + 1][r1] = rw1.y; Ws[c1 + 2][r1] = rw1.z; Ws[c1 + 3][r1] = rw1.w;
        __syncthreads();
        if (k0 + 16 < DIM) {
            ra0 = *(const float4*)&A[(size_t)(m0 + r0) * DIM + k0 + 16 + c0];
            ra1 = *(const float4*)&A[(size_t)(m0 + r1) * DIM + k0 + 16 + c1];
            rw0 = *(const float4*)&W[(size_t)(d0 + r0) * DIM + k0 + 16 + c0];
            rw1 = *(const float4*)&W[(size_t)(d0 + r1) * DIM + k0 + 16 + c1];
        }
#pragma unroll
        for (int k = 0; k < 16; k++) {
            float a[8], w[8];
            *(float4*)&a[0] = *(const float4*)&As[k][ty << 2];
            *(float4*)&a[4] = *(const float4*)&As[k][(ty << 2) + 64];
            *(float4*)&w[0] = *(const float4*)&Ws[k][tx << 2];
            *(float4*)&w[4] = *(const float4*)&Ws[k][(tx << 2) + 64];
#pragma unroll
            for (int i = 0; i < 8; i++)
#pragma unroll
                for (int j = 0; j < 8; j++)
                    acc[i][j] = fmaf(a[i], w[j], acc[i][j]);
        }
        __syncthreads();
    }

    // Scatter epilogue into [b, h, n, hd] layout; tile (128 wide) lies in one
    // of q/k/v since 768 % 128 == 0.
    const int which = d0 / DIM;
    float* dstbase = (which == 0) ? g_q : (which == 1) ? g_k : g_v;

#pragma unroll
    for (int i = 0; i < 8; i++) {
        int m = m0 + (ty << 2) + (i & 3) + ((i >> 2) << 6);
        int b = m >> 11;
        int n = m & 2047;
#pragma unroll
        for (int jh = 0; jh < 2; jh++) {
            int d = d0 + (tx << 2) + (jh << 6);
            int dl = d % DIM;
            int h = dl >> 6, hd = dl & 63;
            float4 v = make_float4(acc[i][jh * 4 + 0], acc[i][jh * 4 + 1],
                                   acc[i][jh * 4 + 2], acc[i][jh * 4 + 3]);
            *(float4*)&dstbase[(((size_t)b * NHEAD + h) * SEQ + n) * HDIM + hd] = v;
        }
    }
}

// ---------------------------------------------------------------------------
// Kernel 2: flash attention over compacted (unmasked) keys.
// 64 query rows/block, 64 threads, one thread = one query row.
// Qs XOR-skewed (stride 64, conflict-free), KVs shared K/V buffer,
// Ss transposed [j][t] score buffer (conflict-free, enables dynamic-j PV).
// ---------------------------------------------------------------------------
__global__ __launch_bounds__(64) void attn_kernel()
{
    __shared__ float Qs[64 * 64];   // skewed: [r][ (d + 4r) & 63 ]
    __shared__ float KVs[64 * 64];  // [j][d]
    __shared__ float Ss[64 * 64];   // [j][t]

    const int t = threadIdx.x;
    const int bh = blockIdx.y;
    const int b = bh / NHEAD, h = bh % NHEAD;
    const int q0 = blockIdx.x * 64;
    const float* qb = g_q + (size_t)bh * SEQ * HDIM;
    const float* kb = g_k + (size_t)bh * SEQ * HDIM;
    const float* vb = g_v + (size_t)bh * SEQ * HDIM;
    float* dst = g_x + (size_t)(b * SEQ + q0 + t) * DIM + h * HDIM;
    const int cnt = g_cnt[b];
    const int* idxb = g_idx + b * SEQ;

    if (cnt == 0) {
        // All keys masked: softmax is uniform -> output = mean of V rows.
        float acc[64];
#pragma unroll
        for (int d = 0; d < 64; d++) acc[d] = 0.f;
        for (int k = 0; k < SEQ; k++) {
#pragma unroll
            for (int d0 = 0; d0 < 64; d0 += 4) {
                float4 v = *(const float4*)&vb[(size_t)k * HDIM + d0];
                acc[d0] += v.x; acc[d0 + 1] += v.y; acc[d0 + 2] += v.z; acc[d0 + 3] += v.w;
            }
        }
        const float inv = 1.f / (float)SEQ;
#pragma unroll
        for (int d0 = 0; d0 < 64; d0 += 4)
            *(float4*)&dst[d0] = make_float4(acc[d0] * inv, acc[d0 + 1] * inv,
                                             acc[d0 + 2] * inv, acc[d0 + 3] * inv);
        return;
    }

    // Load Q tile, skewed
#pragma unroll
    for (int i = 0; i < 16; i++) {
        int qq = t + 64 * i;
        int r = qq >> 4, dq = (qq & 15) << 2;
        float4 v = *(const float4*)&qb[(size_t)(q0 + r) * HDIM + dq];
        *(float4*)&Qs[r * 64 + ((dq + 4 * r) & 63)] = v;
    }

    float o[64];
#pragma unroll
    for (int d = 0; d < 64; d++) o[d] = 0.f;
    float mrun = -INFINITY, lrun = 0.f;
    __syncthreads();

    const int ntiles = (cnt + 63) >> 6;
    for (int tile = 0; tile < ntiles; tile++) {
        const int k0 = tile << 6;

        // K tile via index indirection (row index broadcast from L1)
#pragma unroll
        for (int i = 0; i < 16; i++) {
            int qq = t + 64 * i;
            int r = qq >> 4, dq = (qq & 15) << 2;
            int g = k0 + r;
            int src = (g < cnt) ? __ldg(&idxb[g]) : 0;
            *(float4*)&KVs[r * 64 + dq] = *(const float4*)&kb[(size_t)src * HDIM + dq];
        }
        __syncthreads();

        float s[64];
#pragma unroll
        for (int j = 0; j < 64; j++) s[j] = 0.f;
#pragma unroll 1
        for (int d0 = 0; d0 < 64; d0 += 4) {
            float4 qv = *(const float4*)&Qs[t * 64 + ((d0 + 4 * t) & 63)];
#pragma unroll
            for (int j = 0; j < 64; j++) {
                float4 kv = *(const float4*)&KVs[j * 64 + d0];
                s[j] = fmaf(qv.x, kv.x, s[j]);
                s[j] = fmaf(qv.y, kv.y, s[j]);
                s[j] = fmaf(qv.z, kv.z, s[j]);
                s[j] = fmaf(qv.w, kv.w, s[j]);
            }
        }

        const int valid = cnt - k0;
        float mt = -INFINITY;
#pragma unroll
        for (int j = 0; j < 64; j++) {
            s[j] = (j < valid) ? s[j] * SCALE : -1e30f;
            mt = fmaxf(mt, s[j]);
        }
        float mnew = fmaxf(mrun, mt);
        float alpha = __expf(mrun - mnew); // exp(-inf)=0 on first tile
        float lsum = 0.f;
#pragma unroll
        for (int j = 0; j < 64; j++) {
            s[j] = __expf(s[j] - mnew);
            lsum += s[j];
        }
        lrun = lrun * alpha + lsum;
        mrun = mnew;
#pragma unroll
        for (int d = 0; d < 64; d++) o[d] *= alpha;
#pragma unroll
        for (int j = 0; j < 64; j++) Ss[j * 64 + t] = s[j];
        __syncthreads();

        // V tile (reuse KVs)
#pragma unroll
        for (int i = 0; i < 16; i++) {
            int qq = t + 64 * i;
            int r = qq >> 4, dq = (qq & 15) << 2;
            int g = k0 + r;
            int src = (g < cnt) ? __ldg(&idxb[g]) : 0;
            *(float4*)&KVs[r * 64 + dq] = *(const float4*)&vb[(size_t)src * HDIM + dq];
        }
        __syncthreads();

#pragma unroll 1
        for (int j = 0; j < 64; j++) {
            float p = Ss[j * 64 + t];
#pragma unroll
            for (int d0 = 0; d0 < 64; d0 += 4) {
                float4 vv = *(const float4*)&KVs[j * 64 + d0];
                o[d0]     = fmaf(p, vv.x, o[d0]);
                o[d0 + 1] = fmaf(p, vv.y, o[d0 + 1]);
                o[d0 + 2] = fmaf(p, vv.z, o[d0 + 2]);
                o[d0 + 3] = fmaf(p, vv.w, o[d0 + 3]);
            }
        }
        __syncthreads();
    }

    const float inv = 1.f / lrun;
#pragma unroll
    for (int d0 = 0; d0 < 64; d0 += 4)
        *(float4*)&dst[d0] = make_float4(o[d0] * inv, o[d0 + 1] * inv,
                                         o[d0 + 2] * inv, o[d0 + 3] * inv);
}

// ---------------------------------------------------------------------------
// Kernel 3: FC projection. out[m, d] = sum_c x[m, c] * Wfc[d, c] + b[d]
// Same GEMM structure as qkv_kernel.
// ---------------------------------------------------------------------------
__global__ __launch_bounds__(256) void fc_kernel(
    const float* __restrict__ W, const float* __restrict__ bias,
    float* __restrict__ out)
{
    __shared__ float As[16][132];
    __shared__ float Ws[16][132];

    const int tid = threadIdx.x;
    const int tx = tid & 15;
    const int ty = tid >> 4;
    const int m0 = blockIdx.y << 7;
    const int d0 = blockIdx.x << 7;

    float acc[8][8];
#pragma unroll
    for (int i = 0; i < 8; i++)
#pragma unroll
        for (int j = 0; j < 8; j++) acc[i][j] = 0.f;

    const int r0 = tid >> 2,         c0 = (tid & 3) << 2;
    const int r1 = (tid + 256) >> 2, c1 = (tid & 3) << 2;

    float4 ra0 = *(const float4*)&g_x[(size_t)(m0 + r0) * DIM + c0];
    float4 ra1 = *(const float4*)&g_x[(size_t)(m0 + r1) * DIM + c1];
    float4 rw0 = *(const float4*)&W[(size_t)(d0 + r0) * DIM + c0];
    float4 rw1 = *(const float4*)&W[(size_t)(d0 + r1) * DIM + c1];

    for (int k0 = 0; k0 < DIM; k0 += 16) {
        As[c0 + 0][r0] = ra0.x; As[c0 + 1][r0] = ra0.y; As[c0 + 2][r0] = ra0.z; As[c0 + 3][r0] = ra0.w;
        As[c1 + 0][r1] = ra1.x; As[c1 + 1][r1] = ra1.y; As[c1 + 2][r1] = ra1.z; As[c1 + 3][r1] = ra1.w;
        Ws[c0 + 0][r0] = rw0.x; Ws[c0 + 1][r0] = rw0.y; Ws[c0 + 2][r0] = rw0.z; Ws[c0 + 3][r0] = rw0.w;
        Ws[c1 + 0][r1] = rw1.x; Ws[c1 + 1][r1] = rw1.y; Ws[c1 + 2][r1] = rw1.z; Ws[c1 + 3][r1] = rw1.w;
        __syncthreads();
        if (k0 + 16 < DIM) {
            ra0 = *(const float4*)&g_x[(size_t)(m0 + r0) * DIM + k0 + 16 + c0];
            ra1 = *(const float4*)&g_x[(size_t)(m0 + r1) * DIM + k0 + 16 + c1];
            rw0 = *(const float4*)&W[(size_t)(d0 + r0) * DIM + k0 + 16 + c0];
            rw1 = *(const float4*)&W[(size_t)(d0 + r1) * DIM + k0 + 16 + c1];
        }
#pragma unroll
        for (int k = 0; k < 16; k++) {
            float a[8], w[8];
            *(float4*)&a[0] = *(const float4*)&As[k][ty << 2];
            *(float4*)&a[4] = *(const float4*)&As[k][(ty << 2) + 64];
            *(float4*)&w[0] = *(const float4*)&Ws[k][tx << 2];
            *(float4*)&w[4] = *(const float4*)&Ws[k][(tx << 2) + 64];
#pragma unroll
            for (int i = 0; i < 8; i++)
#pragma unroll
                for (int j = 0; j < 8; j++)
                    acc[i][j] = fmaf(a[i], w[j], acc[i][j]);
        }
        __syncthreads();
    }

#pragma unroll
    for (int i = 0; i < 8; i++) {
        int m = m0 + (ty << 2) + (i & 3) + ((i >> 2) << 6);
#pragma unroll
        for (int jh = 0; jh < 2; jh++) {
            int d = d0 + (tx << 2) + (jh << 6);
            float4 bv = *(const float4*)&bias[d];
            float4 v = make_float4(acc[i][jh * 4 + 0] + bv.x, acc[i][jh * 4 + 1] + bv.y,
                                   acc[i][jh * 4 + 2] + bv.z, acc[i][jh * 4 + 3] + bv.w);
            *(float4*)&out[(size_t)m * DIM + d] = v;
        }
    }
}

// ---------------------------------------------------------------------------
// Launch
// ---------------------------------------------------------------------------
extern "C" void kernel_launch(void* const* d_in, const int* in_sizes, int n_in,
                              void* d_out, int out_size)
{
    const float* inputs = (const float*)d_in[0];
    const int*   pmask  = (const int*)d_in[1];
    const float* w_qkv  = (const float*)d_in[2];
    const float* w_fc   = (const float*)d_in[3];
    const float* b_fc   = (const float*)d_in[4];
    float* out = (float*)d_out;

    compact_kernel<<<BATCH, 256>>>(pmask);
    {
        dim3 grid(QKV_DIM / 128, M_TOTAL / 128); // (18, 32)
        qkv_kernel<<<grid, 256>>>(inputs, w_qkv);
    }
    {
        dim3 grid(SEQ / 64, BATCH * NHEAD);      // (32, 24)
        attn_kernel<<<grid, 64>>>();
    }
    {
        dim3 grid(DIM / 128, M_TOTAL / 128);     // (6, 32)
        fc_kernel<<<grid, 256>>>(w_fc, b_fc, out);
    }
}

// round 3
// speedup vs baseline: 2.8407x; 1.5553x over previous
#include <cuda_runtime.h>
#include <mma.h>
#include <math.h>

using namespace nvcuda;

// Problem constants
#define BATCH 2
#define SEQ 2048
#define DIM 768
#define NHEAD 12
#define HDIM 64
#define QKV_DIM (3 * DIM)     // 2304
#define M_TOTAL (BATCH * SEQ) // 4096
#define SCALE 0.125f          // 64^-0.5

// Scratch (device globals; no allocations allowed)
__device__ float g_q[BATCH * NHEAD * SEQ * HDIM];
__device__ float g_k[BATCH * NHEAD * SEQ * HDIM];
__device__ float g_v[BATCH * NHEAD * SEQ * HDIM];
__device__ float g_x[M_TOTAL * DIM];
__device__ int   g_idx[BATCH * SEQ];
__device__ int   g_cnt[BATCH];

typedef wmma::fragment<wmma::matrix_a, 16, 16, 8, wmma::precision::tf32, wmma::row_major> AFrag;
typedef wmma::fragment<wmma::matrix_b, 16, 16, 8, wmma::precision::tf32, wmma::col_major> BFragCol;
typedef wmma::fragment<wmma::matrix_b, 16, 16, 8, wmma::precision::tf32, wmma::row_major> BFragRow;
typedef wmma::fragment<wmma::accumulator, 16, 16, 8, float> CFrag;

template <class F>
__device__ __forceinline__ void to_tf32(F& f) {
#pragma unroll
    for (int i = 0; i < f.num_elements; i++) f.x[i] = wmma::__float_to_tf32(f.x[i]);
}

// ---------------------------------------------------------------------------
// Kernel 0: per-batch compaction of unmasked key indices (mask <= 0).
// Masked keys get score -1e7; exp underflows to exactly 0 in fp32, so
// dropping them is numerically identical to the reference.
// ---------------------------------------------------------------------------
__global__ void compact_kernel(const int* __restrict__ mask)
{
    __shared__ int cnts[256];
    const int b = blockIdx.x;
    const int t = threadIdx.x;
    const int PER = SEQ / 256; // 8

    int m[PER];
    int local = 0;
#pragma unroll
    for (int i = 0; i < PER; i++) {
        m[i] = mask[b * SEQ + t * PER + i];
        local += (m[i] <= 0);
    }
    cnts[t] = local;
    __syncthreads();
    for (int off = 1; off < 256; off <<= 1) {
        int v = (t >= off) ? cnts[t - off] : 0;
        __syncthreads();
        cnts[t] += v;
        __syncthreads();
    }
    int w = cnts[t] - local;
#pragma unroll
    for (int i = 0; i < PER; i++)
        if (m[i] <= 0) g_idx[b * SEQ + (w++)] = t * PER + i;
    if (t == 255) g_cnt[b] = cnts[255];
}

// ---------------------------------------------------------------------------
// Kernel 1: QKV projection (tf32 wmma). C[m,d] = sum_c A[m,c] * W[d,c].
// 128x128 block tile, 8 warps (2x4), warp tile 64x32, K-chunk 32.
// Epilogue scatters fragments directly into [b,h,n,hd] layout.
// ---------------------------------------------------------------------------
__global__ __launch_bounds__(256) void qkv_kernel(
    const float* __restrict__ A, const float* __restrict__ W)
{
    __shared__ float As[128 * 36];
    __shared__ float Ws[128 * 36];

    const int tid = threadIdx.x;
    const int w = tid >> 5;
    const int wy = w >> 2;      // 0..1 (m)
    const int wx = w & 3;       // 0..3 (d)
    const int m0 = blockIdx.y << 7;
    const int d0 = blockIdx.x << 7;

    CFrag acc[4][2];
#pragma unroll
    for (int i = 0; i < 4; i++)
#pragma unroll
        for (int j = 0; j < 2; j++) wmma::fill_fragment(acc[i][j], 0.f);

    const int r = tid >> 3;
    const int c4 = (tid & 7) << 2;

    float4 pa[4], pw[4];
#pragma unroll
    for (int p = 0; p < 4; p++) {
        pa[p] = *(const float4*)&A[(size_t)(m0 + r + 32 * p) * DIM + c4];
        pw[p] = *(const float4*)&W[(size_t)(d0 + r + 32 * p) * DIM + c4];
    }

    for (int kc = 0; kc < DIM; kc += 32) {
#pragma unroll
        for (int p = 0; p < 4; p++) {
            *(float4*)&As[(r + 32 * p) * 36 + c4] = pa[p];
            *(float4*)&Ws[(r + 32 * p) * 36 + c4] = pw[p];
        }
        __syncthreads();
        if (kc + 32 < DIM) {
#pragma unroll
            for (int p = 0; p < 4; p++) {
                pa[p] = *(const float4*)&A[(size_t)(m0 + r + 32 * p) * DIM + kc + 32 + c4];
                pw[p] = *(const float4*)&W[(size_t)(d0 + r + 32 * p) * DIM + kc + 32 + c4];
            }
        }
#pragma unroll
        for (int ks = 0; ks < 4; ks++) {
            AFrag am[4];
            BFragCol bn[2];
#pragma unroll
            for (int ms = 0; ms < 4; ms++) {
                wmma::load_matrix_sync(am[ms], &As[(wy * 64 + ms * 16) * 36 + ks * 8], 36);
                to_tf32(am[ms]);
            }
#pragma unroll
            for (int ns = 0; ns < 2; ns++) {
                wmma::load_matrix_sync(bn[ns], &Ws[(wx * 32 + ns * 16) * 36 + ks * 8], 36);
                to_tf32(bn[ns]);
            }
#pragma unroll
            for (int ms = 0; ms < 4; ms++)
#pragma unroll
                for (int ns = 0; ns < 2; ns++)
                    wmma::mma_sync(acc[ms][ns], am[ms], bn[ns], acc[ms][ns]);
        }
        __syncthreads();
    }

    // Scatter epilogue into [b,h,n,hd]
    const int bIdx = m0 >> 11;
    const int n0 = (m0 & 2047) + wy * 64;
    const int dg = d0 + wx * 32;
    const int which = dg / DIM;
    float* dstb = (which == 0) ? g_q : (which == 1) ? g_k : g_v;

#pragma unroll
    for (int ms = 0; ms < 4; ms++)
#pragma unroll
        for (int ns = 0; ns < 2; ns++) {
            int dl = (dg % DIM) + ns * 16;
            int h = dl >> 6, hd = dl & 63;
            float* p = dstb + (((size_t)bIdx * NHEAD + h) * SEQ + n0 + ms * 16) * HDIM + hd;
            wmma::store_matrix_sync(p, acc[ms][ns], HDIM, wmma::mem_row_major);
        }
}

// ---------------------------------------------------------------------------
// Kernel 2: flash attention (tf32 wmma) over compacted keys.
// 64 query rows/block, 4 warps; each warp owns a 16-row strip.
// Q preloaded into A-fragments (registers). K/V share KVs buffer;
// S/E shares the Q-load buffer. No max-subtraction needed: |s*SCALE|
// is small (<~25), exp never overflows; normalization divides at end.
// ---------------------------------------------------------------------------
__global__ __launch_bounds__(128) void attn_kernel()
{
    __shared__ float buf1[64 * 68];  // Q tile, then S/E tile
    __shared__ float KVs[64 * 68];   // K tile, then V tile
    __shared__ float lsum[64];
    __shared__ float meanv[64];

    const int tid = threadIdx.x;
    const int warp = tid >> 5;
    const int bh = blockIdx.y;
    const int b = bh / NHEAD, h = bh % NHEAD;
    const int q0 = blockIdx.x * 64;
    const float* qb = g_q + (size_t)bh * SEQ * HDIM;
    const float* kb = g_k + (size_t)bh * SEQ * HDIM;
    const float* vb = g_v + (size_t)bh * SEQ * HDIM;
    const int cnt = g_cnt[b];
    const int* idxb = g_idx + b * SEQ;

    if (cnt == 0) {
        // All keys masked: softmax uniform -> output = mean of V rows.
        if (tid < 64) {
            float acc = 0.f;
            for (int k = 0; k < SEQ; k++) acc += vb[(size_t)k * HDIM + tid];
            meanv[tid] = acc / (float)SEQ;
        }
        __syncthreads();
        int row = tid >> 1, half = tid & 1;
        float* dst = g_x + (size_t)(b * SEQ + q0 + row) * DIM + h * HDIM + half * 32;
#pragma unroll
        for (int c = 0; c < 32; c++) dst[c] = meanv[half * 32 + c];
        return;
    }

    // Load Q tile into buf1
#pragma unroll
    for (int i = 0; i < 8; i++) {
        int idx = tid + 128 * i;
        int r = idx >> 4, c4 = (idx & 15) << 2;
        *(float4*)&buf1[r * 68 + c4] = *(const float4*)&qb[(size_t)(q0 + r) * HDIM + c4];
    }
    if (tid < 64) lsum[tid] = 0.f;
    __syncthreads();

    // Preload Q fragments for this warp's 16-row strip (reused every tile)
    AFrag aq[8];
#pragma unroll
    for (int ks = 0; ks < 8; ks++) {
        wmma::load_matrix_sync(aq[ks], &buf1[(warp * 16) * 68 + ks * 8], 68);
        to_tf32(aq[ks]);
    }

    CFrag ofrag[4];
#pragma unroll
    for (int dn = 0; dn < 4; dn++) wmma::fill_fragment(ofrag[dn], 0.f);

    const int ntiles = (cnt + 63) >> 6;
    for (int tile = 0; tile < ntiles; tile++) {
        const int k0 = tile << 6;
        __syncthreads(); // prev PV done; KVs/buf1 free (also orders Q preload)

        // Gather K tile
#pragma unroll
        for (int i = 0; i < 8; i++) {
            int idx = tid + 128 * i;
            int r = idx >> 4, c4 = (idx & 15) << 2;
            int g = k0 + r;
            int src = (g < cnt) ? __ldg(&idxb[g]) : 0;
            *(float4*)&KVs[r * 68 + c4] = *(const float4*)&kb[(size_t)src * HDIM + c4];
        }
        __syncthreads();

        // S = Q K^T for this warp's strip (16 x 64)
        CFrag sfrag[4];
#pragma unroll
        for (int jn = 0; jn < 4; jn++) wmma::fill_fragment(sfrag[jn], 0.f);
#pragma unroll
        for (int ks = 0; ks < 8; ks++) {
#pragma unroll
            for (int jn = 0; jn < 4; jn++) {
                BFragCol bk;
                wmma::load_matrix_sync(bk, &KVs[(jn * 16) * 68 + ks * 8], 68);
                to_tf32(bk);
                wmma::mma_sync(sfrag[jn], aq[ks], bk, sfrag[jn]);
            }
        }
#pragma unroll
        for (int jn = 0; jn < 4; jn++)
            wmma::store_matrix_sync(&buf1[(warp * 16) * 68 + jn * 16], sfrag[jn], 68,
                                    wmma::mem_row_major);
        __syncthreads();

        // Elementwise exp (+ mask tail) and row-sum accumulation
        {
            const int row = tid >> 1, half = tid & 1;
            const int valid = cnt - k0;
            float* er = &buf1[row * 68 + half * 32];
            float ps = 0.f;
#pragma unroll
            for (int c4 = 0; c4 < 32; c4 += 4) {
                float4 v = *(float4*)&er[c4];
                int jb = half * 32 + c4;
                v.x = (jb + 0 < valid) ? __expf(v.x * SCALE) : 0.f;
                v.y = (jb + 1 < valid) ? __expf(v.y * SCALE) : 0.f;
                v.z = (jb + 2 < valid) ? __expf(v.z * SCALE) : 0.f;
                v.w = (jb + 3 < valid) ? __expf(v.w * SCALE) : 0.f;
                ps += v.x + v.y + v.z + v.w;
                *(float4*)&er[c4] = v;
            }
            ps += __shfl_xor_sync(0xffffffffu, ps, 1);
            if (half == 0) lsum[row] += ps;
        }

        // Gather V tile (overwrite KVs; safe: all S mma reads done at last sync)
#pragma unroll
        for (int i = 0; i < 8; i++) {
            int idx = tid + 128 * i;
            int r = idx >> 4, c4 = (idx & 15) << 2;
            int g = k0 + r;
            int src = (g < cnt) ? __ldg(&idxb[g]) : 0;
            *(float4*)&KVs[r * 68 + c4] = *(const float4*)&vb[(size_t)src * HDIM + c4];
        }
        __syncthreads();

        // O += E V
#pragma unroll
        for (int js = 0; js < 8; js++) {
            AFrag ap;
            wmma::load_matrix_sync(ap, &buf1[(warp * 16) * 68 + js * 8], 68);
            to_tf32(ap);
#pragma unroll
            for (int dn = 0; dn < 4; dn++) {
                BFragRow bv;
                wmma::load_matrix_sync(bv, &KVs[(js * 8) * 68 + dn * 16], 68);
                to_tf32(bv);
                wmma::mma_sync(ofrag[dn], ap, bv, ofrag[dn]);
            }
        }
    }

    __syncthreads();
#pragma unroll
    for (int dn = 0; dn < 4; dn++)
        wmma::store_matrix_sync(&buf1[(warp * 16) * 68 + dn * 16], ofrag[dn], 68,
                                wmma::mem_row_major);
    __syncthreads();

    {
        const int row = tid >> 1, half = tid & 1;
        const float inv = 1.f / lsum[row];
        const float* src = &buf1[row * 68 + half * 32];
        float* dst = g_x + (size_t)(b * SEQ + q0 + row) * DIM + h * HDIM + half * 32;
#pragma unroll
        for (int c4 = 0; c4 < 32; c4 += 4) {
            float4 v = *(const float4*)&src[c4];
            *(float4*)&dst[c4] = make_float4(v.x * inv, v.y * inv, v.z * inv, v.w * inv);
        }
    }
}

// ---------------------------------------------------------------------------
// Kernel 3: FC projection (tf32 wmma). out[m,d] = sum_c x[m,c] * W[d,c].
// Bias added by bias_kernel afterwards.
// ---------------------------------------------------------------------------
__global__ __launch_bounds__(256) void fc_kernel(
    const float* __restrict__ W, float* __restrict__ out)
{
    __shared__ float As[128 * 36];
    __shared__ float Ws[128 * 36];

    const int tid = threadIdx.x;
    const int w = tid >> 5;
    const int wy = w >> 2;
    const int wx = w & 3;
    const int m0 = blockIdx.y << 7;
    const int d0 = blockIdx.x << 7;

    CFrag acc[4][2];
#pragma unroll
    for (int i = 0; i < 4; i++)
#pragma unroll
        for (int j = 0; j < 2; j++) wmma::fill_fragment(acc[i][j], 0.f);

    const int r = tid >> 3;
    const int c4 = (tid & 7) << 2;

    float4 pa[4], pw[4];
#pragma unroll
    for (int p = 0; p < 4; p++) {
        pa[p] = *(const float4*)&g_x[(size_t)(m0 + r + 32 * p) * DIM + c4];
        pw[p] = *(const float4*)&W[(size_t)(d0 + r + 32 * p) * DIM + c4];
    }

    for (int kc = 0; kc < DIM; kc += 32) {
#pragma unroll
        for (int p = 0; p < 4; p++) {
            *(float4*)&As[(r + 32 * p) * 36 + c4] = pa[p];
            *(float4*)&Ws[(r + 32 * p) * 36 + c4] = pw[p];
        }
        __syncthreads();
        if (kc + 32 < DIM) {
#pragma unroll
            for (int p = 0; p < 4; p++) {
                pa[p] = *(const float4*)&g_x[(size_t)(m0 + r + 32 * p) * DIM + kc + 32 + c4];
                pw[p] = *(const float4*)&W[(size_t)(d0 + r + 32 * p) * DIM + kc + 32 + c4];
            }
        }
#pragma unroll
        for (int ks = 0; ks < 4; ks++) {
            AFrag am[4];
            BFragCol bn[2];
#pragma unroll
            for (int ms = 0; ms < 4; ms++) {
                wmma::load_matrix_sync(am[ms], &As[(wy * 64 + ms * 16) * 36 + ks * 8], 36);
                to_tf32(am[ms]);
            }
#pragma unroll
            for (int ns = 0; ns < 2; ns++) {
                wmma::load_matrix_sync(bn[ns], &Ws[(wx * 32 + ns * 16) * 36 + ks * 8], 36);
                to_tf32(bn[ns]);
            }
#pragma unroll
            for (int ms = 0; ms < 4; ms++)
#pragma unroll
                for (int ns = 0; ns < 2; ns++)
                    wmma::mma_sync(acc[ms][ns], am[ms], bn[ns], acc[ms][ns]);
        }
        __syncthreads();
    }

#pragma unroll
    for (int ms = 0; ms < 4; ms++)
#pragma unroll
        for (int ns = 0; ns < 2; ns++) {
            float* p = out + (size_t)(m0 + wy * 64 + ms * 16) * DIM + d0 + wx * 32 + ns * 16;
            wmma::store_matrix_sync(p, acc[ms][ns], DIM, wmma::mem_row_major);
        }
}

// Bias add (b_fc may be nonzero in principle)
__global__ void bias_kernel(float* __restrict__ out, const float* __restrict__ bias)
{
    int i4 = blockIdx.x * blockDim.x + threadIdx.x;    // float4 index
    const int total4 = M_TOTAL * DIM / 4;
    if (i4 >= total4) return;
    int col4 = (i4 % (DIM / 4)) << 2;
    float4 v = *(float4*)&out[i4 * 4];
    float4 bv = *(const float4*)&bias[col4];
    v.x += bv.x; v.y += bv.y; v.z += bv.z; v.w += bv.w;
    *(float4*)&out[i4 * 4] = v;
}

// ---------------------------------------------------------------------------
// Launch
// ---------------------------------------------------------------------------
extern "C" void kernel_launch(void* const* d_in, const int* in_sizes, int n_in,
                              void* d_out, int out_size)
{
    const float* inputs = (const float*)d_in[0];
    const int*   pmask  = (const int*)d_in[1];
    const float* w_qkv  = (const float*)d_in[2];
    const float* w_fc   = (const float*)d_in[3];
    const float* b_fc   = (const float*)d_in[4];
    float* out = (float*)d_out;

    compact_kernel<<<BATCH, 256>>>(pmask);
    {
        dim3 grid(QKV_DIM / 128, M_TOTAL / 128); // (18, 32)
        qkv_kernel<<<grid, 256>>>(inputs, w_qkv);
    }
    {
        dim3 grid(SEQ / 64, BATCH * NHEAD);      // (32, 24)
        attn_kernel<<<grid, 128>>>();
    }
    {
        dim3 grid(DIM / 128, M_TOTAL / 128);     // (6, 32)
        fc_kernel<<<grid, 256>>>(w_fc, out);
    }
    {
        int total4 = M_TOTAL * DIM / 4;
        bias_kernel<<<(total4 + 255) / 256, 256>>>(out, b_fc);
    }
}

// round 4
// speedup vs baseline: 3.3641x; 1.1843x over previous
#include <cuda_runtime.h>
#include <mma.h>
#include <math.h>

using namespace nvcuda;

// Problem constants
#define BATCH 2
#define SEQ 2048
#define DIM 768
#define NHEAD 12
#define HDIM 64
#define QKV_DIM (3 * DIM)     // 2304
#define M_TOTAL (BATCH * SEQ) // 4096
#define SCALE 0.125f          // 64^-0.5

// Scratch (device globals; no allocations allowed)
__device__ float g_q[BATCH * NHEAD * SEQ * HDIM];
__device__ float g_k[BATCH * NHEAD * SEQ * HDIM];
__device__ float g_v[BATCH * NHEAD * SEQ * HDIM];
__device__ float g_x[M_TOTAL * DIM];
__device__ int   g_idx[BATCH * SEQ];
__device__ int   g_cnt[BATCH];

typedef wmma::fragment<wmma::matrix_a, 16, 16, 8, wmma::precision::tf32, wmma::row_major> AFrag;
typedef wmma::fragment<wmma::matrix_b, 16, 16, 8, wmma::precision::tf32, wmma::col_major> BFragCol;
typedef wmma::fragment<wmma::matrix_b, 16, 16, 8, wmma::precision::tf32, wmma::row_major> BFragRow;
typedef wmma::fragment<wmma::accumulator, 16, 16, 8, float> CFrag;

__device__ __forceinline__ float4 tf32x4(float4 v) {
    v.x = wmma::__float_to_tf32(v.x);
    v.y = wmma::__float_to_tf32(v.y);
    v.z = wmma::__float_to_tf32(v.z);
    v.w = wmma::__float_to_tf32(v.w);
    return v;
}

// ---------------------------------------------------------------------------
// Kernel 0: per-batch compaction of unmasked key indices (mask <= 0).
// Masked keys get score -1e7; exp underflows to exactly 0 in fp32, so
// dropping them is numerically identical to the reference.
// ---------------------------------------------------------------------------
__global__ void compact_kernel(const int* __restrict__ mask)
{
    __shared__ int cnts[256];
    const int b = blockIdx.x;
    const int t = threadIdx.x;
    const int PER = SEQ / 256; // 8

    int m[PER];
    int local = 0;
#pragma unroll
    for (int i = 0; i < PER; i++) {
        m[i] = mask[b * SEQ + t * PER + i];
        local += (m[i] <= 0);
    }
    cnts[t] = local;
    __syncthreads();
    for (int off = 1; off < 256; off <<= 1) {
        int v = (t >= off) ? cnts[t - off] : 0;
        __syncthreads();
        cnts[t] += v;
        __syncthreads();
    }
    int w = cnts[t] - local;
#pragma unroll
    for (int i = 0; i < PER; i++)
        if (m[i] <= 0) g_idx[b * SEQ + (w++)] = t * PER + i;
    if (t == 255) g_cnt[b] = cnts[255];
}

// ---------------------------------------------------------------------------
// GEMM config: 128(M) x 64(N) block tile, 4 warps (2x2), 64x32 warp tile,
// BK=16, register prefetch, tf32 conversion done once at smem staging.
// ---------------------------------------------------------------------------
#define BK 16
#define LDA 20  // 16 + 4 pad

// ---------------------------------------------------------------------------
// Kernel 1: QKV projection. C[m,d] = sum_c A[m,c] * W[d,c].
// Epilogue scatters into [b,h,n,hd] layout, tf32-truncated (attention
// would truncate these anyway at its own MMA inputs).
// ---------------------------------------------------------------------------
__global__ __launch_bounds__(128, 4) void qkv_kernel(
    const float* __restrict__ A, const float* __restrict__ W)
{
    __shared__ float As[128 * LDA];
    __shared__ float Ws[64 * LDA];

    const int tid = threadIdx.x;
    const int w = tid >> 5;
    const int wy = w >> 1;      // 0..1 (m)
    const int wx = w & 1;       // 0..1 (n)
    const int m0 = blockIdx.y << 7;
    const int d0 = blockIdx.x << 6;

    CFrag acc[4][2];
#pragma unroll
    for (int i = 0; i < 4; i++)
#pragma unroll
        for (int j = 0; j < 2; j++) wmma::fill_fragment(acc[i][j], 0.f);

    const int ar = tid >> 2;          // 0..31 (A row base, +32*i)
    const int ac4 = (tid & 3) << 2;   // 0,4,8,12

    float4 pa[4], pw[2];
#pragma unroll
    for (int i = 0; i < 4; i++)
        pa[i] = *(const float4*)&A[(size_t)(m0 + ar + 32 * i) * DIM + ac4];
#pragma unroll
    for (int i = 0; i < 2; i++)
        pw[i] = *(const float4*)&W[(size_t)(d0 + ar + 32 * i) * DIM + ac4];

    for (int kc = 0; kc < DIM; kc += BK) {
#pragma unroll
        for (int i = 0; i < 4; i++)
            *(float4*)&As[(ar + 32 * i) * LDA + ac4] = tf32x4(pa[i]);
#pragma unroll
        for (int i = 0; i < 2; i++)
            *(float4*)&Ws[(ar + 32 * i) * LDA + ac4] = tf32x4(pw[i]);
        __syncthreads();
        if (kc + BK < DIM) {
#pragma unroll
            for (int i = 0; i < 4; i++)
                pa[i] = *(const float4*)&A[(size_t)(m0 + ar + 32 * i) * DIM + kc + BK + ac4];
#pragma unroll
            for (int i = 0; i < 2; i++)
                pw[i] = *(const float4*)&W[(size_t)(d0 + ar + 32 * i) * DIM + kc + BK + ac4];
        }
#pragma unroll
        for (int ks = 0; ks < 2; ks++) {
            AFrag am[4];
            BFragCol bn[2];
#pragma unroll
            for (int ms = 0; ms < 4; ms++)
                wmma::load_matrix_sync(am[ms], &As[(wy * 64 + ms * 16) * LDA + ks * 8], LDA);
#pragma unroll
            for (int ns = 0; ns < 2; ns++)
                wmma::load_matrix_sync(bn[ns], &Ws[(wx * 32 + ns * 16) * LDA + ks * 8], LDA);
#pragma unroll
            for (int ms = 0; ms < 4; ms++)
#pragma unroll
                for (int ns = 0; ns < 2; ns++)
                    wmma::mma_sync(acc[ms][ns], am[ms], bn[ns], acc[ms][ns]);
        }
        __syncthreads();
    }

    // Scatter epilogue into [b,h,n,hd], truncated to tf32.
    const int bIdx = m0 >> 11;
    const int n0 = (m0 & 2047) + wy * 64;
    const int dg = d0 + wx * 32;
    const int which = dg / DIM;
    float* dstb = (which == 0) ? g_q : (which == 1) ? g_k : g_v;

#pragma unroll
    for (int ms = 0; ms < 4; ms++)
#pragma unroll
        for (int ns = 0; ns < 2; ns++) {
#pragma unroll
            for (int e = 0; e < acc[ms][ns].num_elements; e++)
                acc[ms][ns].x[e] = wmma::__float_to_tf32(acc[ms][ns].x[e]);
            int dl = (dg % DIM) + ns * 16;
            int h = dl >> 6, hd = dl & 63;
            float* p = dstb + (((size_t)bIdx * NHEAD + h) * SEQ + n0 + ms * 16) * HDIM + hd;
            wmma::store_matrix_sync(p, acc[ms][ns], HDIM, wmma::mem_row_major);
        }
}

// ---------------------------------------------------------------------------
// Kernel 2: flash attention (tf32 wmma) over compacted keys.
// Inputs g_q/g_k/g_v are pre-truncated to tf32 -> no fragment conversion.
// E is truncated at its smem store. No max-subtraction needed (|s*SCALE|
// small, exp can't overflow); normalization divides at end.
// ---------------------------------------------------------------------------
__global__ __launch_bounds__(128) void attn_kernel()
{
    __shared__ float buf1[64 * 68];  // Q tile, then S/E tile
    __shared__ float KVs[64 * 68];   // K tile, then V tile
    __shared__ float lsum[64];
    __shared__ float meanv[64];

    const int tid = threadIdx.x;
    const int warp = tid >> 5;
    const int bh = blockIdx.y;
    const int b = bh / NHEAD, h = bh % NHEAD;
    const int q0 = blockIdx.x * 64;
    const float* qb = g_q + (size_t)bh * SEQ * HDIM;
    const float* kb = g_k + (size_t)bh * SEQ * HDIM;
    const float* vb = g_v + (size_t)bh * SEQ * HDIM;
    const int cnt = g_cnt[b];
    const int* idxb = g_idx + b * SEQ;

    if (cnt == 0) {
        // All keys masked: softmax uniform -> output = mean of V rows.
        if (tid < 64) {
            float acc = 0.f;
            for (int k = 0; k < SEQ; k++) acc += vb[(size_t)k * HDIM + tid];
            meanv[tid] = acc / (float)SEQ;
        }
        __syncthreads();
        int row = tid >> 1, half = tid & 1;
        float* dst = g_x + (size_t)(b * SEQ + q0 + row) * DIM + h * HDIM + half * 32;
#pragma unroll
        for (int c = 0; c < 32; c++) dst[c] = meanv[half * 32 + c];
        return;
    }

    // Load Q tile into buf1 (already tf32-truncated in gmem)
#pragma unroll
    for (int i = 0; i < 8; i++) {
        int idx = tid + 128 * i;
        int r = idx >> 4, c4 = (idx & 15) << 2;
        *(float4*)&buf1[r * 68 + c4] = *(const float4*)&qb[(size_t)(q0 + r) * HDIM + c4];
    }
    if (tid < 64) lsum[tid] = 0.f;
    __syncthreads();

    // Preload Q fragments for this warp's 16-row strip (reused every tile)
    AFrag aq[8];
#pragma unroll
    for (int ks = 0; ks < 8; ks++)
        wmma::load_matrix_sync(aq[ks], &buf1[(warp * 16) * 68 + ks * 8], 68);

    CFrag ofrag[4];
#pragma unroll
    for (int dn = 0; dn < 4; dn++) wmma::fill_fragment(ofrag[dn], 0.f);

    const int ntiles = (cnt + 63) >> 6;
    for (int tile = 0; tile < ntiles; tile++) {
        const int k0 = tile << 6;
        __syncthreads(); // prev PV done; KVs/buf1 free (also orders Q preload)

        // Gather K tile
#pragma unroll
        for (int i = 0; i < 8; i++) {
            int idx = tid + 128 * i;
            int r = idx >> 4, c4 = (idx & 15) << 2;
            int g = k0 + r;
            int src = (g < cnt) ? __ldg(&idxb[g]) : 0;
            *(float4*)&KVs[r * 68 + c4] = *(const float4*)&kb[(size_t)src * HDIM + c4];
        }
        __syncthreads();

        // S = Q K^T for this warp's strip (16 x 64)
        CFrag sfrag[4];
#pragma unroll
        for (int jn = 0; jn < 4; jn++) wmma::fill_fragment(sfrag[jn], 0.f);
#pragma unroll
        for (int ks = 0; ks < 8; ks++) {
#pragma unroll
            for (int jn = 0; jn < 4; jn++) {
                BFragCol bk;
                wmma::load_matrix_sync(bk, &KVs[(jn * 16) * 68 + ks * 8], 68);
                wmma::mma_sync(sfrag[jn], aq[ks], bk, sfrag[jn]);
            }
        }
#pragma unroll
        for (int jn = 0; jn < 4; jn++)
            wmma::store_matrix_sync(&buf1[(warp * 16) * 68 + jn * 16], sfrag[jn], 68,
                                    wmma::mem_row_major);
        __syncthreads();

        // Elementwise exp (+ mask tail), tf32-truncate, row-sum accumulate
        {
            const int row = tid >> 1, half = tid & 1;
            const int valid = cnt - k0;
            float* er = &buf1[row * 68 + half * 32];
            float ps = 0.f;
#pragma unroll
            for (int c4 = 0; c4 < 32; c4 += 4) {
                float4 v = *(float4*)&er[c4];
                int jb = half * 32 + c4;
                v.x = (jb + 0 < valid) ? __expf(v.x * SCALE) : 0.f;
                v.y = (jb + 1 < valid) ? __expf(v.y * SCALE) : 0.f;
                v.z = (jb + 2 < valid) ? __expf(v.z * SCALE) : 0.f;
                v.w = (jb + 3 < valid) ? __expf(v.w * SCALE) : 0.f;
                ps += v.x + v.y + v.z + v.w;
                *(float4*)&er[c4] = tf32x4(v);
            }
            ps += __shfl_xor_sync(0xffffffffu, ps, 1);
            if (half == 0) lsum[row] += ps;
        }

        // Gather V tile (overwrite KVs; safe: all S mma reads done at last sync)
#pragma unroll
        for (int i = 0; i < 8; i++) {
            int idx = tid + 128 * i;
            int r = idx >> 4, c4 = (idx & 15) << 2;
            int g = k0 + r;
            int src = (g < cnt) ? __ldg(&idxb[g]) : 0;
            *(float4*)&KVs[r * 68 + c4] = *(const float4*)&vb[(size_t)src * HDIM + c4];
        }
        __syncthreads();

        // O += E V
#pragma unroll
        for (int js = 0; js < 8; js++) {
            AFrag ap;
            wmma::load_matrix_sync(ap, &buf1[(warp * 16) * 68 + js * 8], 68);
#pragma unroll
            for (int dn = 0; dn < 4; dn++) {
                BFragRow bv;
                wmma::load_matrix_sync(bv, &KVs[(js * 8) * 68 + dn * 16], 68);
                wmma::mma_sync(ofrag[dn], ap, bv, ofrag[dn]);
            }
        }
    }

    __syncthreads();
#pragma unroll
    for (int dn = 0; dn < 4; dn++)
        wmma::store_matrix_sync(&buf1[(warp * 16) * 68 + dn * 16], ofrag[dn], 68,
                                wmma::mem_row_major);
    __syncthreads();

    {
        const int row = tid >> 1, half = tid & 1;
        const float inv = 1.f / lsum[row];
        const float* src = &buf1[row * 68 + half * 32];
        float* dst = g_x + (size_t)(b * SEQ + q0 + row) * DIM + h * HDIM + half * 32;
#pragma unroll
        for (int c4 = 0; c4 < 32; c4 += 4) {
            float4 v = *(const float4*)&src[c4];
            *(float4*)&dst[c4] = make_float4(v.x * inv, v.y * inv, v.z * inv, v.w * inv);
        }
    }
}

// ---------------------------------------------------------------------------
// Kernel 3: FC projection. out[m,d] = sum_c x[m,c] * W[d,c].
// ---------------------------------------------------------------------------
__global__ __launch_bounds__(128, 4) void fc_kernel(
    const float* __restrict__ W, float* __restrict__ out)
{
    __shared__ float As[128 * LDA];
    __shared__ float Ws[64 * LDA];

    const int tid = threadIdx.x;
    const int w = tid >> 5;
    const int wy = w >> 1;
    const int wx = w & 1;
    const int m0 = blockIdx.y << 7;
    const int d0 = blockIdx.x << 6;

    CFrag acc[4][2];
#pragma unroll
    for (int i = 0; i < 4; i++)
#pragma unroll
        for (int j = 0; j < 2; j++) wmma::fill_fragment(acc[i][j], 0.f);

    const int ar = tid >> 2;
    const int ac4 = (tid & 3) << 2;

    float4 pa[4], pw[2];
#pragma unroll
    for (int i = 0; i < 4; i++)
        pa[i] = *(const float4*)&g_x[(size_t)(m0 + ar + 32 * i) * DIM + ac4];
#pragma unroll
    for (int i = 0; i < 2; i++)
        pw[i] = *(const float4*)&W[(size_t)(d0 + ar + 32 * i) * DIM + ac4];

    for (int kc = 0; kc < DIM; kc += BK) {
#pragma unroll
        for (int i = 0; i < 4; i++)
            *(float4*)&As[(ar + 32 * i) * LDA + ac4] = tf32x4(pa[i]);
#pragma unroll
        for (int i = 0; i < 2; i++)
            *(float4*)&Ws[(ar + 32 * i) * LDA + ac4] = tf32x4(pw[i]);
        __syncthreads();
        if (kc + BK < DIM) {
#pragma unroll
            for (int i = 0; i < 4; i++)
                pa[i] = *(const float4*)&g_x[(size_t)(m0 + ar + 32 * i) * DIM + kc + BK + ac4];
#pragma unroll
            for (int i = 0; i < 2; i++)
                pw[i] = *(const float4*)&W[(size_t)(d0 + ar + 32 * i) * DIM + kc + BK + ac4];
        }
#pragma unroll
        for (int ks = 0; ks < 2; ks++) {
            AFrag am[4];
            BFragCol bn[2];
#pragma unroll
            for (int ms = 0; ms < 4; ms++)
                wmma::load_matrix_sync(am[ms], &As[(wy * 64 + ms * 16) * LDA + ks * 8], LDA);
#pragma unroll
            for (int ns = 0; ns < 2; ns++)
                wmma::load_matrix_sync(bn[ns], &Ws[(wx * 32 + ns * 16) * LDA + ks * 8], LDA);
#pragma unroll
            for (int ms = 0; ms < 4; ms++)
#pragma unroll
                for (int ns = 0; ns < 2; ns++)
                    wmma::mma_sync(acc[ms][ns], am[ms], bn[ns], acc[ms][ns]);
        }
        __syncthreads();
    }

#pragma unroll
    for (int ms = 0; ms < 4; ms++)
#pragma unroll
        for (int ns = 0; ns < 2; ns++) {
            float* p = out + (size_t)(m0 + wy * 64 + ms * 16) * DIM + d0 + wx * 32 + ns * 16;
            wmma::store_matrix_sync(p, acc[ms][ns], DIM, wmma::mem_row_major);
        }
}

// Bias add (b_fc may be nonzero in principle)
__global__ void bias_kernel(float* __restrict__ out, const float* __restrict__ bias)
{
    int i4 = blockIdx.x * blockDim.x + threadIdx.x;    // float4 index
    const int total4 = M_TOTAL * DIM / 4;
    if (i4 >= total4) return;
    int col4 = (i4 % (DIM / 4)) << 2;
    float4 v = *(float4*)&out[i4 * 4];
    float4 bv = *(const float4*)&bias[col4];
    v.x += bv.x; v.y += bv.y; v.z += bv.z; v.w += bv.w;
    *(float4*)&out[i4 * 4] = v;
}

// ---------------------------------------------------------------------------
// Launch
// ---------------------------------------------------------------------------
extern "C" void kernel_launch(void* const* d_in, const int* in_sizes, int n_in,
                              void* d_out, int out_size)
{
    const float* inputs = (const float*)d_in[0];
    const int*   pmask  = (const int*)d_in[1];
    const float* w_qkv  = (const float*)d_in[2];
    const float* w_fc   = (const float*)d_in[3];
    const float* b_fc   = (const float*)d_in[4];
    float* out = (float*)d_out;

    compact_kernel<<<BATCH, 256>>>(pmask);
    {
        dim3 grid(QKV_DIM / 64, M_TOTAL / 128); // (36, 32) = 1152 CTAs
        qkv_kernel<<<grid, 128>>>(inputs, w_qkv);
    }
    {
        dim3 grid(SEQ / 64, BATCH * NHEAD);     // (32, 24)
        attn_kernel<<<grid, 128>>>();
    }
    {
        dim3 grid(DIM / 64, M_TOTAL / 128);     // (12, 32) = 384 CTAs
        fc_kernel<<<grid, 128>>>(w_fc, out);
    }
    {
        int total4 = M_TOTAL * DIM / 4;
        bias_kernel<<<(total4 + 255) / 256, 256>>>(out, b_fc);
    }
}

// round 5
// speedup vs baseline: 3.7054x; 1.1014x over previous
#include <cuda_runtime.h>
#include <mma.h>
#include <math.h>

using namespace nvcuda;

// Problem constants
#define BATCH 2
#define SEQ 2048
#define DIM 768
#define NHEAD 12
#define HDIM 64
#define QKV_DIM (3 * DIM)     // 2304
#define M_TOTAL (BATCH * SEQ) // 4096
#define SCALE 0.125f          // 64^-0.5

// Scratch (device globals; no allocations allowed)
__device__ float g_q[BATCH * NHEAD * SEQ * HDIM];
__device__ float g_k[BATCH * NHEAD * SEQ * HDIM];
__device__ float g_v[BATCH * NHEAD * SEQ * HDIM];
__device__ float g_x[M_TOTAL * DIM];
__device__ int   g_idx[BATCH * SEQ];
__device__ int   g_cnt[BATCH];

typedef wmma::fragment<wmma::matrix_a, 16, 16, 8, wmma::precision::tf32, wmma::row_major> AFrag;
typedef wmma::fragment<wmma::matrix_b, 16, 16, 8, wmma::precision::tf32, wmma::col_major> BFragCol;
typedef wmma::fragment<wmma::matrix_b, 16, 16, 8, wmma::precision::tf32, wmma::row_major> BFragRow;
typedef wmma::fragment<wmma::accumulator, 16, 16, 8, float> CFrag;

__device__ __forceinline__ float4 tf32x4(float4 v) {
    v.x = wmma::__float_to_tf32(v.x);
    v.y = wmma::__float_to_tf32(v.y);
    v.z = wmma::__float_to_tf32(v.z);
    v.w = wmma::__float_to_tf32(v.w);
    return v;
}

// ---------------------------------------------------------------------------
// Kernel 0: per-batch compaction of unmasked key indices (mask <= 0).
// Masked keys get score -1e7; exp underflows to exactly 0 in fp32, so
// dropping them is numerically identical to the reference.
// ---------------------------------------------------------------------------
__global__ void compact_kernel(const int* __restrict__ mask)
{
    __shared__ int cnts[256];
    const int b = blockIdx.x;
    const int t = threadIdx.x;
    const int PER = SEQ / 256; // 8

    int m[PER];
    int local = 0;
#pragma unroll
    for (int i = 0; i < PER; i++) {
        m[i] = mask[b * SEQ + t * PER + i];
        local += (m[i] <= 0);
    }
    cnts[t] = local;
    __syncthreads();
    for (int off = 1; off < 256; off <<= 1) {
        int v = (t >= off) ? cnts[t - off] : 0;
        __syncthreads();
        cnts[t] += v;
        __syncthreads();
    }
    int w = cnts[t] - local;
#pragma unroll
    for (int i = 0; i < PER; i++)
        if (m[i] <= 0) g_idx[b * SEQ + (w++)] = t * PER + i;
    if (t == 255) g_cnt[b] = cnts[255];
}

// ---------------------------------------------------------------------------
// GEMM config: 128(M) x 64(N) block tile, 4 warps (2x2), 64x32 warp tile,
// BK=16, double-buffered smem, ONE __syncthreads per k-iter.
// ---------------------------------------------------------------------------
#define BK 16
#define LDA 20  // 16 + 4 pad

// ---------------------------------------------------------------------------
// Kernel 1: QKV projection. C[m,d] = sum_c A[m,c] * W[d,c].
// ---------------------------------------------------------------------------
__global__ __launch_bounds__(128, 3) void qkv_kernel(
    const float* __restrict__ A, const float* __restrict__ W)
{
    __shared__ float As[2][128 * LDA];
    __shared__ float Ws[2][64 * LDA];

    const int tid = threadIdx.x;
    const int w = tid >> 5;
    const int wy = w >> 1;      // 0..1 (m)
    const int wx = w & 1;       // 0..1 (n)
    const int m0 = blockIdx.y << 7;
    const int d0 = blockIdx.x << 6;

    CFrag acc[4][2];
#pragma unroll
    for (int i = 0; i < 4; i++)
#pragma unroll
        for (int j = 0; j < 2; j++) wmma::fill_fragment(acc[i][j], 0.f);

    const int ar = tid >> 2;          // 0..31
    const int ac4 = (tid & 3) << 2;   // 0,4,8,12

    float4 pa[4], pw[2];
#pragma unroll
    for (int i = 0; i < 4; i++)
        pa[i] = *(const float4*)&A[(size_t)(m0 + ar + 32 * i) * DIM + ac4];
#pragma unroll
    for (int i = 0; i < 2; i++)
        pw[i] = *(const float4*)&W[(size_t)(d0 + ar + 32 * i) * DIM + ac4];
#pragma unroll
    for (int i = 0; i < 4; i++)
        *(float4*)&As[0][(ar + 32 * i) * LDA + ac4] = tf32x4(pa[i]);
#pragma unroll
    for (int i = 0; i < 2; i++)
        *(float4*)&Ws[0][(ar + 32 * i) * LDA + ac4] = tf32x4(pw[i]);
    __syncthreads();

    int buf = 0;
    for (int kc = 0; kc < DIM; kc += BK) {
        const bool more = (kc + BK < DIM);
        if (more) {
#pragma unroll
            for (int i = 0; i < 4; i++)
                pa[i] = *(const float4*)&A[(size_t)(m0 + ar + 32 * i) * DIM + kc + BK + ac4];
#pragma unroll
            for (int i = 0; i < 2; i++)
                pw[i] = *(const float4*)&W[(size_t)(d0 + ar + 32 * i) * DIM + kc + BK + ac4];
        }
#pragma unroll
        for (int ks = 0; ks < 2; ks++) {
            AFrag am[4];
            BFragCol bn[2];
#pragma unroll
            for (int ms = 0; ms < 4; ms++)
                wmma::load_matrix_sync(am[ms], &As[buf][(wy * 64 + ms * 16) * LDA + ks * 8], LDA);
#pragma unroll
            for (int ns = 0; ns < 2; ns++)
                wmma::load_matrix_sync(bn[ns], &Ws[buf][(wx * 32 + ns * 16) * LDA + ks * 8], LDA);
#pragma unroll
            for (int ms = 0; ms < 4; ms++)
#pragma unroll
                for (int ns = 0; ns < 2; ns++)
                    wmma::mma_sync(acc[ms][ns], am[ms], bn[ns], acc[ms][ns]);
        }
        if (more) {
#pragma unroll
            for (int i = 0; i < 4; i++)
                *(float4*)&As[buf ^ 1][(ar + 32 * i) * LDA + ac4] = tf32x4(pa[i]);
#pragma unroll
            for (int i = 0; i < 2; i++)
                *(float4*)&Ws[buf ^ 1][(ar + 32 * i) * LDA + ac4] = tf32x4(pw[i]);
            __syncthreads();
            buf ^= 1;
        }
    }

    // Scatter epilogue into [b,h,n,hd], truncated to tf32.
    const int bIdx = m0 >> 11;
    const int n0 = (m0 & 2047) + wy * 64;
    const int dg = d0 + wx * 32;
    const int which = dg / DIM;
    float* dstb = (which == 0) ? g_q : (which == 1) ? g_k : g_v;

#pragma unroll
    for (int ms = 0; ms < 4; ms++)
#pragma unroll
        for (int ns = 0; ns < 2; ns++) {
#pragma unroll
            for (int e = 0; e < acc[ms][ns].num_elements; e++)
                acc[ms][ns].x[e] = wmma::__float_to_tf32(acc[ms][ns].x[e]);
            int dl = (dg % DIM) + ns * 16;
            int h = dl >> 6, hd = dl & 63;
            float* p = dstb + (((size_t)bIdx * NHEAD + h) * SEQ + n0 + ms * 16) * HDIM + hd;
            wmma::store_matrix_sync(p, acc[ms][ns], HDIM, wmma::mem_row_major);
        }
}

// ---------------------------------------------------------------------------
// Kernel 2: flash attention (tf32 wmma) over compacted keys, with
// register-prefetched gathers: V-gather issues before the S mma, next-tile
// K-gather issues before the PV mma, so both hide under tensor work.
// ---------------------------------------------------------------------------
__global__ __launch_bounds__(128) void attn_kernel()
{
    __shared__ float buf1[64 * 68];  // Q tile, then S/E tile
    __shared__ float KVs[64 * 68];   // K tile, then V tile
    __shared__ float lsum[64];
    __shared__ float meanv[64];

    const int tid = threadIdx.x;
    const int warp = tid >> 5;
    const int bh = blockIdx.y;
    const int b = bh / NHEAD, h = bh % NHEAD;
    const int q0 = blockIdx.x * 64;
    const float* qb = g_q + (size_t)bh * SEQ * HDIM;
    const float* kb = g_k + (size_t)bh * SEQ * HDIM;
    const float* vb = g_v + (size_t)bh * SEQ * HDIM;
    const int cnt = g_cnt[b];
    const int* idxb = g_idx + b * SEQ;

    if (cnt == 0) {
        // All keys masked: softmax uniform -> output = mean of V rows.
        if (tid < 64) {
            float acc = 0.f;
            for (int k = 0; k < SEQ; k++) acc += vb[(size_t)k * HDIM + tid];
            meanv[tid] = acc / (float)SEQ;
        }
        __syncthreads();
        int row = tid >> 1, half = tid & 1;
        float* dst = g_x + (size_t)(b * SEQ + q0 + row) * DIM + h * HDIM + half * 32;
#pragma unroll
        for (int c = 0; c < 32; c++) dst[c] = meanv[half * 32 + c];
        return;
    }

    // Per-thread gather slots: idx = tid + 128*i -> (row, col4)
    const int gr[2] = { tid >> 4, (tid + 128) >> 4 }; // pattern repeats +16 per i
    const int gc4 = (tid & 15) << 2;

    // Load Q tile into buf1 (already tf32 in gmem)
#pragma unroll
    for (int i = 0; i < 8; i++) {
        int r = gr[i & 1] + (i >> 1) * 16;
        *(float4*)&buf1[r * 68 + gc4] = *(const float4*)&qb[(size_t)(q0 + r) * HDIM + gc4];
    }
    if (tid < 64) lsum[tid] = 0.f;
    __syncthreads();

    // Preload Q fragments for this warp's 16-row strip
    AFrag aq[8];
#pragma unroll
    for (int ks = 0; ks < 8; ks++)
        wmma::load_matrix_sync(aq[ks], &buf1[(warp * 16) * 68 + ks * 8], 68);

    CFrag ofrag[4];
#pragma unroll
    for (int dn = 0; dn < 4; dn++) wmma::fill_fragment(ofrag[dn], 0.f);

    const int ntiles = (cnt + 63) >> 6;

    // Prologue: gather indices + K tile 0 into registers
    int src[8];
    float4 kreg[8];
#pragma unroll
    for (int i = 0; i < 8; i++) {
        int r = gr[i & 1] + (i >> 1) * 16;
        src[i] = (r < cnt) ? __ldg(&idxb[r]) : 0;
        kreg[i] = *(const float4*)&kb[(size_t)src[i] * HDIM + gc4];
    }

    for (int tile = 0; tile < ntiles; tile++) {
        const int k0 = tile << 6;
        __syncthreads(); // prev PV reads of KVs/buf1 complete

        // Commit K registers to smem
#pragma unroll
        for (int i = 0; i < 8; i++) {
            int r = gr[i & 1] + (i >> 1) * 16;
            *(float4*)&KVs[r * 68 + gc4] = kreg[i];
        }
        __syncthreads();

        // Issue V gather for THIS tile (same indices) — overlaps S mma
        float4 vreg[8];
#pragma unroll
        for (int i = 0; i < 8; i++)
            vreg[i] = *(const float4*)&vb[(size_t)src[i] * HDIM + gc4];

        // S = Q K^T for this warp's strip (16 x 64)
        CFrag sfrag[4];
#pragma unroll
        for (int jn = 0; jn < 4; jn++) wmma::fill_fragment(sfrag[jn], 0.f);
#pragma unroll
        for (int ks = 0; ks < 8; ks++) {
#pragma unroll
            for (int jn = 0; jn < 4; jn++) {
                BFragCol bk;
                wmma::load_matrix_sync(bk, &KVs[(jn * 16) * 68 + ks * 8], 68);
                wmma::mma_sync(sfrag[jn], aq[ks], bk, sfrag[jn]);
            }
        }
#pragma unroll
        for (int jn = 0; jn < 4; jn++)
            wmma::store_matrix_sync(&buf1[(warp * 16) * 68 + jn * 16], sfrag[jn], 68,
                                    wmma::mem_row_major);
        __syncthreads(); // all KVs reads + S stores done

        // Elementwise exp (+ mask tail), tf32-truncate, row-sum accumulate
        {
            const int row = tid >> 1, half = tid & 1;
            const int valid = cnt - k0;
            float* er = &buf1[row * 68 + half * 32];
            float ps = 0.f;
#pragma unroll
            for (int c4 = 0; c4 < 32; c4 += 4) {
                float4 v = *(float4*)&er[c4];
                int jb = half * 32 + c4;
                v.x = (jb + 0 < valid) ? __expf(v.x * SCALE) : 0.f;
                v.y = (jb + 1 < valid) ? __expf(v.y * SCALE) : 0.f;
                v.z = (jb + 2 < valid) ? __expf(v.z * SCALE) : 0.f;
                v.w = (jb + 3 < valid) ? __expf(v.w * SCALE) : 0.f;
                ps += v.x + v.y + v.z + v.w;
                *(float4*)&er[c4] = tf32x4(v);
            }
            ps += __shfl_xor_sync(0xffffffffu, ps, 1);
            if (half == 0) lsum[row] += ps;
        }

        // Commit V registers to smem (KVs reads finished at last sync)
#pragma unroll
        for (int i = 0; i < 8; i++) {
            int r = gr[i & 1] + (i >> 1) * 16;
            *(float4*)&KVs[r * 68 + gc4] = vreg[i];
        }

        // Issue K gather for NEXT tile — overlaps PV mma
        if (tile + 1 < ntiles) {
            const int kn = k0 + 64;
#pragma unroll
            for (int i = 0; i < 8; i++) {
                int r = gr[i & 1] + (i >> 1) * 16;
                int g = kn + r;
                src[i] = (g < cnt) ? __ldg(&idxb[g]) : 0;
                kreg[i] = *(const float4*)&kb[(size_t)src[i] * HDIM + gc4];
            }
        }
        __syncthreads(); // V + E visible to all warps

        // O += E V
#pragma unroll
        for (int js = 0; js < 8; js++) {
            AFrag ap;
            wmma::load_matrix_sync(ap, &buf1[(warp * 16) * 68 + js * 8], 68);
#pragma unroll
            for (int dn = 0; dn < 4; dn++) {
                BFragRow bv;
                wmma::load_matrix_sync(bv, &KVs[(js * 8) * 68 + dn * 16], 68);
                wmma::mma_sync(ofrag[dn], ap, bv, ofrag[dn]);
            }
        }
    }

    __syncthreads();
#pragma unroll
    for (int dn = 0; dn < 4; dn++)
        wmma::store_matrix_sync(&buf1[(warp * 16) * 68 + dn * 16], ofrag[dn], 68,
                                wmma::mem_row_major);
    __syncthreads();

    {
        const int row = tid >> 1, half = tid & 1;
        const float inv = 1.f / lsum[row];
        const float* srcp = &buf1[row * 68 + half * 32];
        float* dst = g_x + (size_t)(b * SEQ + q0 + row) * DIM + h * HDIM + half * 32;
#pragma unroll
        for (int c4 = 0; c4 < 32; c4 += 4) {
            float4 v = *(const float4*)&srcp[c4];
            *(float4*)&dst[c4] = make_float4(v.x * inv, v.y * inv, v.z * inv, v.w * inv);
        }
    }
}

// ---------------------------------------------------------------------------
// Kernel 3: FC projection. out[m,d] = sum_c x[m,c] * W[d,c].
// ---------------------------------------------------------------------------
__global__ __launch_bounds__(128, 3) void fc_kernel(
    const float* __restrict__ W, float* __restrict__ out)
{
    __shared__ float As[2][128 * LDA];
    __shared__ float Ws[2][64 * LDA];

    const int tid = threadIdx.x;
    const int w = tid >> 5;
    const int wy = w >> 1;
    const int wx = w & 1;
    const int m0 = blockIdx.y << 7;
    const int d0 = blockIdx.x << 6;

    CFrag acc[4][2];
#pragma unroll
    for (int i = 0; i < 4; i++)
#pragma unroll
        for (int j = 0; j < 2; j++) wmma::fill_fragment(acc[i][j], 0.f);

    const int ar = tid >> 2;
    const int ac4 = (tid & 3) << 2;

    float4 pa[4], pw[2];
#pragma unroll
    for (int i = 0; i < 4; i++)
        pa[i] = *(const float4*)&g_x[(size_t)(m0 + ar + 32 * i) * DIM + ac4];
#pragma unroll
    for (int i = 0; i < 2; i++)
        pw[i] = *(const float4*)&W[(size_t)(d0 + ar + 32 * i) * DIM + ac4];
#pragma unroll
    for (int i = 0; i < 4; i++)
        *(float4*)&As[0][(ar + 32 * i) * LDA + ac4] = tf32x4(pa[i]);
#pragma unroll
    for (int i = 0; i < 2; i++)
        *(float4*)&Ws[0][(ar + 32 * i) * LDA + ac4] = tf32x4(pw[i]);
    __syncthreads();

    int buf = 0;
    for (int kc = 0; kc < DIM; kc += BK) {
        const bool more = (kc + BK < DIM);
        if (more) {
#pragma unroll
            for (int i = 0; i < 4; i++)
                pa[i] = *(const float4*)&g_x[(size_t)(m0 + ar + 32 * i) * DIM + kc + BK + ac4];
#pragma unroll
            for (int i = 0; i < 2; i++)
                pw[i] = *(const float4*)&W[(size_t)(d0 + ar + 32 * i) * DIM + kc + BK + ac4];
        }
#pragma unroll
        for (int ks = 0; ks < 2; ks++) {
            AFrag am[4];
            BFragCol bn[2];
#pragma unroll
            for (int ms = 0; ms < 4; ms++)
                wmma::load_matrix_sync(am[ms], &As[buf][(wy * 64 + ms * 16) * LDA + ks * 8], LDA);
#pragma unroll
            for (int ns = 0; ns < 2; ns++)
                wmma::load_matrix_sync(bn[ns], &Ws[buf][(wx * 32 + ns * 16) * LDA + ks * 8], LDA);
#pragma unroll
            for (int ms = 0; ms < 4; ms++)
#pragma unroll
                for (int ns = 0; ns < 2; ns++)
                    wmma::mma_sync(acc[ms][ns], am[ms], bn[ns], acc[ms][ns]);
        }
        if (more) {
#pragma unroll
            for (int i = 0; i < 4; i++)
                *(float4*)&As[buf ^ 1][(ar + 32 * i) * LDA + ac4] = tf32x4(pa[i]);
#pragma unroll
            for (int i = 0; i < 2; i++)
                *(float4*)&Ws[buf ^ 1][(ar + 32 * i) * LDA + ac4] = tf32x4(pw[i]);
            __syncthreads();
            buf ^= 1;
        }
    }

#pragma unroll
    for (int ms = 0; ms < 4; ms++)
#pragma unroll
        for (int ns = 0; ns < 2; ns++) {
            float* p = out + (size_t)(m0 + wy * 64 + ms * 16) * DIM + d0 + wx * 32 + ns * 16;
            wmma::store_matrix_sync(p, acc[ms][ns], DIM, wmma::mem_row_major);
        }
}

// Bias add (b_fc may be nonzero in principle)
__global__ void bias_kernel(float* __restrict__ out, const float* __restrict__ bias)
{
    int i4 = blockIdx.x * blockDim.x + threadIdx.x;
    const int total4 = M_TOTAL * DIM / 4;
    if (i4 >= total4) return;
    int col4 = (i4 % (DIM / 4)) << 2;
    float4 v = *(float4*)&out[i4 * 4];
    float4 bv = *(const float4*)&bias[col4];
    v.x += bv.x; v.y += bv.y; v.z += bv.z; v.w += bv.w;
    *(float4*)&out[i4 * 4] = v;
}

// ---------------------------------------------------------------------------
// Launch
// ---------------------------------------------------------------------------
extern "C" void kernel_launch(void* const* d_in, const int* in_sizes, int n_in,
                              void* d_out, int out_size)
{
    const float* inputs = (const float*)d_in[0];
    const int*   pmask  = (const int*)d_in[1];
    const float* w_qkv  = (const float*)d_in[2];
    const float* w_fc   = (const float*)d_in[3];
    const float* b_fc   = (const float*)d_in[4];
    float* out = (float*)d_out;

    compact_kernel<<<BATCH, 256>>>(pmask);
    {
        dim3 grid(QKV_DIM / 64, M_TOTAL / 128); // (36, 32) = 1152 CTAs
        qkv_kernel<<<grid, 128>>>(inputs, w_qkv);
    }
    {
        dim3 grid(SEQ / 64, BATCH * NHEAD);     // (32, 24)
        attn_kernel<<<grid, 128>>>();
    }
    {
        dim3 grid(DIM / 64, M_TOTAL / 128);     // (12, 32) = 384 CTAs
        fc_kernel<<<grid, 128>>>(w_fc, out);
    }
    {
        int total4 = M_TOTAL * DIM / 4;
        bias_kernel<<<(total4 + 255) / 256, 256>>>(out, b_fc);
    }
}

// round 6
// speedup vs baseline: 3.7295x; 1.0065x over previous
#include <cuda_runtime.h>
#include <mma.h>
#include <math.h>

using namespace nvcuda;

// Problem constants
#define BATCH 2
#define SEQ 2048
#define DIM 768
#define NHEAD 12
#define HDIM 64
#define QKV_DIM (3 * DIM)     // 2304
#define M_TOTAL (BATCH * SEQ) // 4096
#define SCALE 0.125f          // 64^-0.5

// Scratch (device globals; no allocations allowed)
__device__ float g_q[BATCH * NHEAD * SEQ * HDIM];
__device__ float g_k[BATCH * NHEAD * SEQ * HDIM];
__device__ float g_v[BATCH * NHEAD * SEQ * HDIM];
__device__ float g_x[M_TOTAL * DIM];
__device__ int   g_idx[BATCH * SEQ];
__device__ int   g_cnt[BATCH];

typedef wmma::fragment<wmma::matrix_a, 16, 16, 8, wmma::precision::tf32, wmma::row_major> AFrag;
typedef wmma::fragment<wmma::matrix_b, 16, 16, 8, wmma::precision::tf32, wmma::col_major> BFragCol;
typedef wmma::fragment<wmma::matrix_b, 16, 16, 8, wmma::precision::tf32, wmma::row_major> BFragRow;
typedef wmma::fragment<wmma::accumulator, 16, 16, 8, float> CFrag;

__device__ __forceinline__ float4 tf32x4(float4 v) {
    v.x = wmma::__float_to_tf32(v.x);
    v.y = wmma::__float_to_tf32(v.y);
    v.z = wmma::__float_to_tf32(v.z);
    v.w = wmma::__float_to_tf32(v.w);
    return v;
}

// ---------------------------------------------------------------------------
// Kernel 0: per-batch compaction of unmasked key indices (mask <= 0).
// Masked keys get score -1e7; exp underflows to exactly 0 in fp32, so
// dropping them is numerically identical to the reference.
// ---------------------------------------------------------------------------
__global__ void compact_kernel(const int* __restrict__ mask)
{
    __shared__ int cnts[256];
    const int b = blockIdx.x;
    const int t = threadIdx.x;
    const int PER = SEQ / 256; // 8

    int m[PER];
    int local = 0;
#pragma unroll
    for (int i = 0; i < PER; i++) {
        m[i] = mask[b * SEQ + t * PER + i];
        local += (m[i] <= 0);
    }
    cnts[t] = local;
    __syncthreads();
    for (int off = 1; off < 256; off <<= 1) {
        int v = (t >= off) ? cnts[t - off] : 0;
        __syncthreads();
        cnts[t] += v;
        __syncthreads();
    }
    int w = cnts[t] - local;
#pragma unroll
    for (int i = 0; i < PER; i++)
        if (m[i] <= 0) g_idx[b * SEQ + (w++)] = t * PER + i;
    if (t == 255) g_cnt[b] = cnts[255];
}

#define BK 16
#define LDA 20  // 16 + 4 pad

// ---------------------------------------------------------------------------
// Kernel 1: QKV projection. C[m,d] = sum_c A[m,c] * W[d,c].
// 128x128 block tile, 4 warps (2x2), warp tile 64x64 (16 mmas : 8 frag loads),
// register prefetch, single smem buffer.
// ---------------------------------------------------------------------------
__global__ __launch_bounds__(128) void qkv_kernel(
    const float* __restrict__ A, const float* __restrict__ W)
{
    __shared__ float As[128 * LDA];
    __shared__ float Ws[128 * LDA];

    const int tid = threadIdx.x;
    const int w = tid >> 5;
    const int wy = w >> 1;      // 0..1 (m)
    const int wx = w & 1;       // 0..1 (n)
    const int m0 = blockIdx.y << 7;
    const int d0 = blockIdx.x << 7;

    CFrag acc[4][4];
#pragma unroll
    for (int i = 0; i < 4; i++)
#pragma unroll
        for (int j = 0; j < 4; j++) wmma::fill_fragment(acc[i][j], 0.f);

    const int ar = tid >> 2;          // 0..31
    const int ac4 = (tid & 3) << 2;   // 0,4,8,12

    float4 pa[4], pw[4];
#pragma unroll
    for (int i = 0; i < 4; i++) {
        pa[i] = *(const float4*)&A[(size_t)(m0 + ar + 32 * i) * DIM + ac4];
        pw[i] = *(const float4*)&W[(size_t)(d0 + ar + 32 * i) * DIM + ac4];
    }

    for (int kc = 0; kc < DIM; kc += BK) {
#pragma unroll
        for (int i = 0; i < 4; i++) {
            *(float4*)&As[(ar + 32 * i) * LDA + ac4] = tf32x4(pa[i]);
            *(float4*)&Ws[(ar + 32 * i) * LDA + ac4] = tf32x4(pw[i]);
        }
        __syncthreads();
        if (kc + BK < DIM) {
#pragma unroll
            for (int i = 0; i < 4; i++) {
                pa[i] = *(const float4*)&A[(size_t)(m0 + ar + 32 * i) * DIM + kc + BK + ac4];
                pw[i] = *(const float4*)&W[(size_t)(d0 + ar + 32 * i) * DIM + kc + BK + ac4];
            }
        }
#pragma unroll
        for (int ks = 0; ks < 2; ks++) {
            AFrag am[4];
            BFragCol bn[4];
#pragma unroll
            for (int ms = 0; ms < 4; ms++)
                wmma::load_matrix_sync(am[ms], &As[(wy * 64 + ms * 16) * LDA + ks * 8], LDA);
#pragma unroll
            for (int ns = 0; ns < 4; ns++)
                wmma::load_matrix_sync(bn[ns], &Ws[(wx * 64 + ns * 16) * LDA + ks * 8], LDA);
#pragma unroll
            for (int ms = 0; ms < 4; ms++)
#pragma unroll
                for (int ns = 0; ns < 4; ns++)
                    wmma::mma_sync(acc[ms][ns], am[ms], bn[ns], acc[ms][ns]);
        }
        __syncthreads();
    }

    // Scatter epilogue into [b,h,n,hd], truncated to tf32.
    const int bIdx = m0 >> 11;
    const int n0 = (m0 & 2047) + wy * 64;
    const int dg = d0 + wx * 64;         // 64-col span; d0 % 768 in {0,128,...}
    const int which = dg / DIM;
    float* dstb = (which == 0) ? g_q : (which == 1) ? g_k : g_v;

#pragma unroll
    for (int ms = 0; ms < 4; ms++)
#pragma unroll
        for (int ns = 0; ns < 4; ns++) {
#pragma unroll
            for (int e = 0; e < acc[ms][ns].num_elements; e++)
                acc[ms][ns].x[e] = wmma::__float_to_tf32(acc[ms][ns].x[e]);
            int dl = (dg % DIM) + ns * 16;
            int h = dl >> 6, hd = dl & 63;
            float* p = dstb + (((size_t)bIdx * NHEAD + h) * SEQ + n0 + ms * 16) * HDIM + hd;
            wmma::store_matrix_sync(p, acc[ms][ns], HDIM, wmma::mem_row_major);
        }
}

// ---------------------------------------------------------------------------
// Kernel 2: flash attention (tf32 wmma) over compacted keys.
// 128 query rows/block (256 thr, 8 warps), 32-row KV tiles.
// Each block reads the full compacted K/V once -> half the gather traffic
// of 64-row blocks. Register-prefetched gathers overlap the mma phases.
// ---------------------------------------------------------------------------
__global__ __launch_bounds__(256) void attn_kernel()
{
    __shared__ float buf1[128 * 68]; // Q tile, then S/E tile, then O tile
    __shared__ float KVs[32 * 68];   // K tile, then V tile
    __shared__ float lsum[128];
    __shared__ float meanv[64];

    const int tid = threadIdx.x;
    const int warp = tid >> 5;
    const int bh = blockIdx.y;
    const int b = bh / NHEAD, h = bh % NHEAD;
    const int q0 = blockIdx.x * 128;
    const float* qb = g_q + (size_t)bh * SEQ * HDIM;
    const float* kb = g_k + (size_t)bh * SEQ * HDIM;
    const float* vb = g_v + (size_t)bh * SEQ * HDIM;
    const int cnt = g_cnt[b];
    const int* idxb = g_idx + b * SEQ;

    if (cnt == 0) {
        // All keys masked: softmax uniform -> output = mean of V rows.
        if (tid < 64) {
            float acc = 0.f;
            for (int k = 0; k < SEQ; k++) acc += vb[(size_t)k * HDIM + tid];
            meanv[tid] = acc / (float)SEQ;
        }
        __syncthreads();
        int row = tid >> 1, half = tid & 1;
        float* dst = g_x + (size_t)(b * SEQ + q0 + row) * DIM + h * HDIM + half * 32;
#pragma unroll
        for (int c = 0; c < 32; c++) dst[c] = meanv[half * 32 + c];
        return;
    }

    const int lr = tid >> 4;            // 0..15
    const int gc4 = (tid & 15) << 2;    // 0..60

    // Load Q tile (128 x 64) into buf1
#pragma unroll
    for (int i = 0; i < 8; i++) {
        int r = lr + 16 * i;
        *(float4*)&buf1[r * 68 + gc4] = *(const float4*)&qb[(size_t)(q0 + r) * HDIM + gc4];
    }
    if (tid < 128) lsum[tid] = 0.f;
    __syncthreads();

    // Preload Q fragments for this warp's 16-row strip
    AFrag aq[8];
#pragma unroll
    for (int ks = 0; ks < 8; ks++)
        wmma::load_matrix_sync(aq[ks], &buf1[(warp * 16) * 68 + ks * 8], 68);

    CFrag ofrag[4];
#pragma unroll
    for (int dn = 0; dn < 4; dn++) wmma::fill_fragment(ofrag[dn], 0.f);

    const int ntiles = (cnt + 31) >> 5;

    // Prologue: gather indices + K tile 0 into registers (32 rows x 64 cols)
    int src[2];
    float4 kreg[2];
#pragma unroll
    for (int i = 0; i < 2; i++) {
        int r = lr + 16 * i;
        src[i] = (r < cnt) ? __ldg(&idxb[r]) : 0;
        kreg[i] = *(const float4*)&kb[(size_t)src[i] * HDIM + gc4];
    }

    for (int tile = 0; tile < ntiles; tile++) {
        const int k0 = tile << 5;
        __syncthreads(); // prev PV reads of KVs/buf1 complete

        // Commit K registers to smem
#pragma unroll
        for (int i = 0; i < 2; i++)
            *(float4*)&KVs[(lr + 16 * i) * 68 + gc4] = kreg[i];
        __syncthreads();

        // Issue V gather for THIS tile (same indices) — overlaps S mma
        float4 vreg[2];
#pragma unroll
        for (int i = 0; i < 2; i++)
            vreg[i] = *(const float4*)&vb[(size_t)src[i] * HDIM + gc4];

        // S = Q K^T for this warp's strip (16 x 32)
        CFrag sfrag[2];
#pragma unroll
        for (int jn = 0; jn < 2; jn++) wmma::fill_fragment(sfrag[jn], 0.f);
#pragma unroll
        for (int ks = 0; ks < 8; ks++) {
#pragma unroll
            for (int jn = 0; jn < 2; jn++) {
                BFragCol bk;
                wmma::load_matrix_sync(bk, &KVs[(jn * 16) * 68 + ks * 8], 68);
                wmma::mma_sync(sfrag[jn], aq[ks], bk, sfrag[jn]);
            }
        }
#pragma unroll
        for (int jn = 0; jn < 2; jn++)
            wmma::store_matrix_sync(&buf1[(warp * 16) * 68 + jn * 16], sfrag[jn], 68,
                                    wmma::mem_row_major);
        __syncthreads(); // all KVs reads + S stores done

        // Elementwise exp (+ mask tail), tf32-truncate, row-sum accumulate
        {
            const int row = tid >> 1, half = tid & 1;
            const int valid = cnt - k0;
            float* er = &buf1[row * 68 + half * 16];
            float ps = 0.f;
#pragma unroll
            for (int c4 = 0; c4 < 16; c4 += 4) {
                float4 v = *(float4*)&er[c4];
                int jb = half * 16 + c4;
                v.x = (jb + 0 < valid) ? __expf(v.x * SCALE) : 0.f;
                v.y = (jb + 1 < valid) ? __expf(v.y * SCALE) : 0.f;
                v.z = (jb + 2 < valid) ? __expf(v.z * SCALE) : 0.f;
                v.w = (jb + 3 < valid) ? __expf(v.w * SCALE) : 0.f;
                ps += v.x + v.y + v.z + v.w;
                *(float4*)&er[c4] = tf32x4(v);
            }
            ps += __shfl_xor_sync(0xffffffffu, ps, 1);
            if (half == 0) lsum[row] += ps;
        }

        // Commit V registers to smem (KVs reads finished at last sync)
#pragma unroll
        for (int i = 0; i < 2; i++)
            *(float4*)&KVs[(lr + 16 * i) * 68 + gc4] = vreg[i];

        // Issue K gather for NEXT tile — overlaps PV mma
        if (tile + 1 < ntiles) {
            const int kn = k0 + 32;
#pragma unroll
            for (int i = 0; i < 2; i++) {
                int g = kn + lr + 16 * i;
                src[i] = (g < cnt) ? __ldg(&idxb[g]) : 0;
                kreg[i] = *(const float4*)&kb[(size_t)src[i] * HDIM + gc4];
            }
        }
        __syncthreads(); // V + E visible to all warps

        // O += E V  (E is 16x32 per warp, V is 32x64)
#pragma unroll
        for (int js = 0; js < 4; js++) {
            AFrag ap;
            wmma::load_matrix_sync(ap, &buf1[(warp * 16) * 68 + js * 8], 68);
#pragma unroll
            for (int dn = 0; dn < 4; dn++) {
                BFragRow bv;
                wmma::load_matrix_sync(bv, &KVs[(js * 8) * 68 + dn * 16], 68);
                wmma::mma_sync(ofrag[dn], ap, bv, ofrag[dn]);
            }
        }
    }

    __syncthreads();
#pragma unroll
    for (int dn = 0; dn < 4; dn++)
        wmma::store_matrix_sync(&buf1[(warp * 16) * 68 + dn * 16], ofrag[dn], 68,
                                wmma::mem_row_major);
    __syncthreads();

    {
        const int row = tid >> 1, half = tid & 1;
        const float inv = 1.f / lsum[row];
        const float* srcp = &buf1[row * 68 + half * 32];
        float* dst = g_x + (size_t)(b * SEQ + q0 + row) * DIM + h * HDIM + half * 32;
#pragma unroll
        for (int c4 = 0; c4 < 32; c4 += 4) {
            float4 v = *(const float4*)&srcp[c4];
            *(float4*)&dst[c4] = make_float4(v.x * inv, v.y * inv, v.z * inv, v.w * inv);
        }
    }
}

// ---------------------------------------------------------------------------
// Kernel 3: FC projection. out[m,d] = sum_c x[m,c] * W[d,c].
// Keeps the 128x64 / 4-warp shape (grid 384 — occupancy-limited already).
// ---------------------------------------------------------------------------
__global__ __launch_bounds__(128, 3) void fc_kernel(
    const float* __restrict__ W, float* __restrict__ out)
{
    __shared__ float As[2][128 * LDA];
    __shared__ float Ws[2][64 * LDA];

    const int tid = threadIdx.x;
    const int w = tid >> 5;
    const int wy = w >> 1;
    const int wx = w & 1;
    const int m0 = blockIdx.y << 7;
    const int d0 = blockIdx.x << 6;

    CFrag acc[4][2];
#pragma unroll
    for (int i = 0; i < 4; i++)
#pragma unroll
        for (int j = 0; j < 2; j++) wmma::fill_fragment(acc[i][j], 0.f);

    const int ar = tid >> 2;
    const int ac4 = (tid & 3) << 2;

    float4 pa[4], pw[2];
#pragma unroll
    for (int i = 0; i < 4; i++)
        pa[i] = *(const float4*)&g_x[(size_t)(m0 + ar + 32 * i) * DIM + ac4];
#pragma unroll
    for (int i = 0; i < 2; i++)
        pw[i] = *(const float4*)&W[(size_t)(d0 + ar + 32 * i) * DIM + ac4];
#pragma unroll
    for (int i = 0; i < 4; i++)
        *(float4*)&As[0][(ar + 32 * i) * LDA + ac4] = tf32x4(pa[i]);
#pragma unroll
    for (int i = 0; i < 2; i++)
        *(float4*)&Ws[0][(ar + 32 * i) * LDA + ac4] = tf32x4(pw[i]);
    __syncthreads();

    int buf = 0;
    for (int kc = 0; kc < DIM; kc += BK) {
        const bool more = (kc + BK < DIM);
        if (more) {
#pragma unroll
            for (int i = 0; i < 4; i++)
                pa[i] = *(const float4*)&g_x[(size_t)(m0 + ar + 32 * i) * DIM + kc + BK + ac4];
#pragma unroll
            for (int i = 0; i < 2; i++)
                pw[i] = *(const float4*)&W[(size_t)(d0 + ar + 32 * i) * DIM + kc + BK + ac4];
        }
#pragma unroll
        for (int ks = 0; ks < 2; ks++) {
            AFrag am[4];
            BFragCol bn[2];
#pragma unroll
            for (int ms = 0; ms < 4; ms++)
                wmma::load_matrix_sync(am[ms], &As[buf][(wy * 64 + ms * 16) * LDA + ks * 8], LDA);
#pragma unroll
            for (int ns = 0; ns < 2; ns++)
                wmma::load_matrix_sync(bn[ns], &Ws[buf][(wx * 32 + ns * 16) * LDA + ks * 8], LDA);
#pragma unroll
            for (int ms = 0; ms < 4; ms++)
#pragma unroll
                for (int ns = 0; ns < 2; ns++)
                    wmma::mma_sync(acc[ms][ns], am[ms], bn[ns], acc[ms][ns]);
        }
        if (more) {
#pragma unroll
            for (int i = 0; i < 4; i++)
                *(float4*)&As[buf ^ 1][(ar + 32 * i) * LDA + ac4] = tf32x4(pa[i]);
#pragma unroll
            for (int i = 0; i < 2; i++)
                *(float4*)&Ws[buf ^ 1][(ar + 32 * i) * LDA + ac4] = tf32x4(pw[i]);
            __syncthreads();
            buf ^= 1;
        }
    }

#pragma unroll
    for (int ms = 0; ms < 4; ms++)
#pragma unroll
        for (int ns = 0; ns < 2; ns++) {
            float* p = out + (size_t)(m0 + wy * 64 + ms * 16) * DIM + d0 + wx * 32 + ns * 16;
            wmma::store_matrix_sync(p, acc[ms][ns], DIM, wmma::mem_row_major);
        }
}

// Bias add (b_fc may be nonzero in principle)
__global__ void bias_kernel(float* __restrict__ out, const float* __restrict__ bias)
{
    int i4 = blockIdx.x * blockDim.x + threadIdx.x;
    const int total4 = M_TOTAL * DIM / 4;
    if (i4 >= total4) return;
    int col4 = (i4 % (DIM / 4)) << 2;
    float4 v = *(float4*)&out[i4 * 4];
    float4 bv = *(const float4*)&bias[col4];
    v.x += bv.x; v.y += bv.y; v.z += bv.z; v.w += bv.w;
    *(float4*)&out[i4 * 4] = v;
}

// ---------------------------------------------------------------------------
// Launch
// ---------------------------------------------------------------------------
extern "C" void kernel_launch(void* const* d_in, const int* in_sizes, int n_in,
                              void* d_out, int out_size)
{
    const float* inputs = (const float*)d_in[0];
    const int*   pmask  = (const int*)d_in[1];
    const float* w_qkv  = (const float*)d_in[2];
    const float* w_fc   = (const float*)d_in[3];
    const float* b_fc   = (const float*)d_in[4];
    float* out = (float*)d_out;

    compact_kernel<<<BATCH, 256>>>(pmask);
    {
        dim3 grid(QKV_DIM / 128, M_TOTAL / 128); // (18, 32) = 576 CTAs
        qkv_kernel<<<grid, 128>>>(inputs, w_qkv);
    }
    {
        dim3 grid(SEQ / 128, BATCH * NHEAD);     // (16, 24) = 384 CTAs
        attn_kernel<<<grid, 256>>>();
    }
    {
        dim3 grid(DIM / 64, M_TOTAL / 128);      // (12, 32) = 384 CTAs
        fc_kernel<<<grid, 128>>>(w_fc, out);
    }
    {
        int total4 = M_TOTAL * DIM / 4;
        bias_kernel<<<(total4 + 255) / 256, 256>>>(out, b_fc);
    }
}